// round 1
// baseline (speedup 1.0000x reference)
#include <cuda_runtime.h>
#include <math.h>

#define B_ 16
#define N_ 1024
#define D_ 2048
#define E_ 8
#define H_ 512
#define A_ 256
#define L_ 64
#define C_ 8
#define NPAIR 32   // B_ * TOP_K

// ---- scratch (static device globals; no allocation in kernel_launch) ----
__device__ float g_r[B_ * H_];                       // 32 KB  router pooled
__device__ float g_h[(size_t)NPAIR * N_ * H_];       // 64 MB  selected-expert hidden
__device__ float g_scores[NPAIR * N_];               // 128 KB attention scores
__device__ int   g_sel_e[NPAIR];
__device__ float g_sel_w[NPAIR];

// ---------------------------------------------------------------------------
// K0: zero the router accumulator (needed every graph replay)
// ---------------------------------------------------------------------------
__global__ void k_zero() {
    int i = blockIdx.x * blockDim.x + threadIdx.x;
    if (i < B_ * H_) g_r[i] = 0.f;
}

// ---------------------------------------------------------------------------
// K1: router GEMM  r[b,h] = mean_n relu(x[b,n,:] @ router_W[:,h] + rb[h])
// X: [B*N, D] row-major, W: [D, H] row-major. Tile 64x64x16, 256 thr, 4x4 micro.
// ---------------------------------------------------------------------------
__global__ __launch_bounds__(256) void k_router_gemm(
    const float* __restrict__ X, const float* __restrict__ W,
    const float* __restrict__ rb) {
    __shared__ float As[64][17];
    __shared__ float Bs[16][64];
    __shared__ float red[16][64];
    const int tid = threadIdx.x;
    const int tx = tid & 15, ty = tid >> 4;
    const int m0 = blockIdx.y * 64;
    const int n0 = blockIdx.x * 64;
    const int lrow = tid >> 2, lk = (tid & 3) * 4;
    const int brow = tid >> 4, bcol = (tid & 15) * 4;

    float acc[4][4] = {};
    const float* xp = X + (size_t)(m0 + lrow) * D_ + lk;
    const float* wp = W + (size_t)brow * H_ + n0 + bcol;

    for (int k0 = 0; k0 < D_; k0 += 16) {
        float4 a4 = *(const float4*)(xp + k0);
        As[lrow][lk + 0] = a4.x; As[lrow][lk + 1] = a4.y;
        As[lrow][lk + 2] = a4.z; As[lrow][lk + 3] = a4.w;
        *(float4*)&Bs[brow][bcol] = *(const float4*)(wp + (size_t)k0 * H_);
        __syncthreads();
        #pragma unroll
        for (int kk = 0; kk < 16; kk++) {
            float4 bb = *(float4*)&Bs[kk][tx * 4];
            #pragma unroll
            for (int i = 0; i < 4; i++) {
                float av = As[ty * 4 + i][kk];
                acc[i][0] += av * bb.x; acc[i][1] += av * bb.y;
                acc[i][2] += av * bb.z; acc[i][3] += av * bb.w;
            }
        }
        __syncthreads();
    }
    // epilogue: relu(+bias), reduce the 64 rows (all same batch b), atomic
    #pragma unroll
    for (int j = 0; j < 4; j++) {
        float bc = rb[n0 + tx * 4 + j];
        float s = 0.f;
        #pragma unroll
        for (int i = 0; i < 4; i++) s += fmaxf(acc[i][j] + bc, 0.f);
        red[ty][tx * 4 + j] = s;
    }
    __syncthreads();
    if (tid < 64) {
        float s = 0.f;
        #pragma unroll
        for (int yy = 0; yy < 16; yy++) s += red[yy][tid];
        int b = m0 / N_;
        atomicAdd(&g_r[b * H_ + n0 + tid], s * (1.f / N_));
    }
}

// ---------------------------------------------------------------------------
// K2: router head: logits = r@fc_W + fc_b, softmax -> g_soft out,
//     top-2 select + renorm weights; zero latent/logits output region.
// ---------------------------------------------------------------------------
__global__ void k_router_head(const float* __restrict__ fcW,
                              const float* __restrict__ fcb,
                              float* __restrict__ out) {
    __shared__ float lg[B_][E_];
    int t = threadIdx.x;
    if (t < B_ * E_) {
        int b = t / E_, e = t % E_;
        float s = fcb[e];
        for (int h = 0; h < H_; h++) s += g_r[b * H_ + h] * fcW[h * E_ + e];
        lg[b][e] = s;
    }
    __syncthreads();
    if (t < B_) {
        int b = t;
        float m = lg[b][0];
        #pragma unroll
        for (int e = 1; e < E_; e++) m = fmaxf(m, lg[b][e]);
        float p[E_]; float s = 0.f;
        #pragma unroll
        for (int e = 0; e < E_; e++) { p[e] = expf(lg[b][e] - m); s += p[e]; }
        float inv = 1.f / s;
        #pragma unroll
        for (int e = 0; e < E_; e++) {
            p[e] *= inv;
            out[B_ * L_ + B_ * C_ + b * E_ + e] = p[e];   // g_soft
        }
        int i0 = 0;
        #pragma unroll
        for (int e = 1; e < E_; e++) if (p[e] > p[i0]) i0 = e;
        int i1 = (i0 == 0) ? 1 : 0;
        #pragma unroll
        for (int e = 0; e < E_; e++) if (e != i1 && e != i0 && p[e] > p[i1]) i1 = e;
        float denom = p[i0] + p[i1] + 1e-8f;
        g_sel_e[2 * b + 0] = i0; g_sel_w[2 * b + 0] = p[i0] / denom;
        g_sel_e[2 * b + 1] = i1; g_sel_w[2 * b + 1] = p[i1] / denom;
    }
    for (int i = t; i < B_ * L_ + B_ * C_; i += blockDim.x) out[i] = 0.f;
}

// ---------------------------------------------------------------------------
// K3: selected-expert hidden GEMM: h = relu(x_b @ eW1[e] + eb1[e])
// only the 32 top-2 (b, e) pairs. Same tiling as K1.
// ---------------------------------------------------------------------------
__global__ __launch_bounds__(256) void k_expert_gemm(
    const float* __restrict__ X, const float* __restrict__ eW1,
    const float* __restrict__ eb1) {
    __shared__ float As[64][17];
    __shared__ float Bs[16][64];
    const int pair = blockIdx.z;
    const int e = g_sel_e[pair];
    const int b = pair >> 1;
    const int tid = threadIdx.x;
    const int tx = tid & 15, ty = tid >> 4;
    const int m0 = blockIdx.y * 64;
    const int n0 = blockIdx.x * 64;
    const int lrow = tid >> 2, lk = (tid & 3) * 4;
    const int brow = tid >> 4, bcol = (tid & 15) * 4;

    float acc[4][4] = {};
    const float* xp = X + (size_t)b * N_ * D_ + (size_t)(m0 + lrow) * D_ + lk;
    const float* wp = eW1 + (size_t)e * D_ * H_ + (size_t)brow * H_ + n0 + bcol;

    for (int k0 = 0; k0 < D_; k0 += 16) {
        float4 a4 = *(const float4*)(xp + k0);
        As[lrow][lk + 0] = a4.x; As[lrow][lk + 1] = a4.y;
        As[lrow][lk + 2] = a4.z; As[lrow][lk + 3] = a4.w;
        *(float4*)&Bs[brow][bcol] = *(const float4*)(wp + (size_t)k0 * H_);
        __syncthreads();
        #pragma unroll
        for (int kk = 0; kk < 16; kk++) {
            float4 bb = *(float4*)&Bs[kk][tx * 4];
            #pragma unroll
            for (int i = 0; i < 4; i++) {
                float av = As[ty * 4 + i][kk];
                acc[i][0] += av * bb.x; acc[i][1] += av * bb.y;
                acc[i][2] += av * bb.z; acc[i][3] += av * bb.w;
            }
        }
        __syncthreads();
    }
    float* hp = g_h + (size_t)pair * N_ * H_;
    #pragma unroll
    for (int i = 0; i < 4; i++) {
        int row = m0 + ty * 4 + i;
        #pragma unroll
        for (int j = 0; j < 4; j++) {
            int col = n0 + tx * 4 + j;
            hp[(size_t)row * H_ + col] = fmaxf(acc[i][j] + eb1[e * H_ + col], 0.f);
        }
    }
}

// ---------------------------------------------------------------------------
// K4: fused attention scores: per (pair, n):
//   s = sum_a tanh(h.Wv[:,a]+bv) * sigmoid(h.Wu[:,a]+bu) * ew[a]  + ebw
// 16 n-rows staged in SMEM per block; thread a owns column a of Wv/Wu.
// ---------------------------------------------------------------------------
__global__ __launch_bounds__(256) void k_scores(
    const float* __restrict__ eWv, const float* __restrict__ ebv,
    const float* __restrict__ eWu, const float* __restrict__ ebu,
    const float* __restrict__ ew, const float* __restrict__ ebw) {
    __shared__ float hs[16][H_];       // 32 KB
    __shared__ float part[16][8];
    const int pair = blockIdx.y;
    const int n0 = blockIdx.x * 16;
    const int e = g_sel_e[pair];
    const int tid = threadIdx.x;

    const float4* src = (const float4*)(g_h + ((size_t)pair * N_ + n0) * H_);
    float4* dst = (float4*)&hs[0][0];
    for (int i = tid; i < 16 * H_ / 4; i += 256) dst[i] = src[i];
    __syncthreads();

    const int a = tid;
    const float* Wv = eWv + (size_t)e * H_ * A_ + a;
    const float* Wu = eWu + (size_t)e * H_ * A_ + a;
    float accV[16] = {}, accU[16] = {};
    for (int h = 0; h < H_; h += 2) {
        float wv0 = Wv[(size_t)h * A_],       wu0 = Wu[(size_t)h * A_];
        float wv1 = Wv[(size_t)(h + 1) * A_], wu1 = Wu[(size_t)(h + 1) * A_];
        #pragma unroll
        for (int r = 0; r < 16; r++) {
            float2 hv = *(const float2*)&hs[r][h];
            accV[r] += hv.x * wv0 + hv.y * wv1;
            accU[r] += hv.x * wu0 + hv.y * wu1;
        }
    }
    const float bv = ebv[e * A_ + a], bu = ebu[e * A_ + a], wgt = ew[e * A_ + a];
    const int lane = tid & 31, warp = tid >> 5;
    #pragma unroll
    for (int r = 0; r < 16; r++) {
        float av = tanhf(accV[r] + bv);
        float au = 1.f / (1.f + expf(-(accU[r] + bu)));
        float v = av * au * wgt;
        v += __shfl_xor_sync(0xffffffffu, v, 16);
        v += __shfl_xor_sync(0xffffffffu, v, 8);
        v += __shfl_xor_sync(0xffffffffu, v, 4);
        v += __shfl_xor_sync(0xffffffffu, v, 2);
        v += __shfl_xor_sync(0xffffffffu, v, 1);
        if (lane == 0) part[r][warp] = v;
    }
    __syncthreads();
    if (tid < 16) {
        float s = ebw[e];
        #pragma unroll
        for (int w = 0; w < 8; w++) s += part[tid][w];
        g_scores[pair * N_ + n0 + tid] = s;
    }
}

// ---------------------------------------------------------------------------
// K5: per pair: softmax over N, pooled = attn^T h, latent/logit heads,
//     weighted atomic combine into d_out.
// ---------------------------------------------------------------------------
__global__ __launch_bounds__(256) void k_final(
    const float* __restrict__ eW2, const float* __restrict__ eb2,
    const float* __restrict__ eWc, const float* __restrict__ ebc,
    float* __restrict__ out) {
    __shared__ float attn[N_];
    __shared__ float red[256];
    __shared__ float pooled[H_];
    __shared__ float lat[L_];
    const int pair = blockIdx.x;
    const int e = g_sel_e[pair], b = pair >> 1;
    const float w = g_sel_w[pair];
    const int t = threadIdx.x;

    const float* sc = g_scores + pair * N_;
    float m = -1e30f;
    for (int i = t; i < N_; i += 256) { float v = sc[i]; attn[i] = v; m = fmaxf(m, v); }
    red[t] = m; __syncthreads();
    for (int s = 128; s > 0; s >>= 1) {
        if (t < s) red[t] = fmaxf(red[t], red[t + s]);
        __syncthreads();
    }
    m = red[0]; __syncthreads();
    float ssum = 0.f;
    for (int i = t; i < N_; i += 256) { float ev = expf(attn[i] - m); attn[i] = ev; ssum += ev; }
    red[t] = ssum; __syncthreads();
    for (int s = 128; s > 0; s >>= 1) {
        if (t < s) red[t] += red[t + s];
        __syncthreads();
    }
    const float inv = 1.f / red[0];

    const float* hp = g_h + (size_t)pair * N_ * H_;
    for (int c = t; c < H_; c += 256) {
        float acc = 0.f;
        #pragma unroll 4
        for (int n = 0; n < N_; n++) acc += attn[n] * hp[(size_t)n * H_ + c];
        pooled[c] = acc * inv;
    }
    __syncthreads();
    if (t < L_) {
        float acc = eb2[e * L_ + t];
        for (int h = 0; h < H_; h++) acc += pooled[h] * eW2[((size_t)e * H_ + h) * L_ + t];
        float lv = fmaxf(acc, 0.f);
        lat[t] = lv;
        atomicAdd(&out[b * L_ + t], w * lv);
    }
    __syncthreads();
    if (t < C_) {
        float acc = ebc[e * C_ + t];
        #pragma unroll
        for (int l = 0; l < L_; l++) acc += lat[l] * eWc[((size_t)e * L_ + l) * C_ + t];
        atomicAdd(&out[B_ * L_ + b * C_ + t], w * acc);
    }
}

// ---------------------------------------------------------------------------
extern "C" void kernel_launch(void* const* d_in, const int* in_sizes, int n_in,
                              void* d_out, int out_size) {
    const float* x        = (const float*)d_in[0];
    const float* router_W = (const float*)d_in[1];
    const float* router_b = (const float*)d_in[2];
    const float* fc_W     = (const float*)d_in[3];
    const float* fc_b     = (const float*)d_in[4];
    const float* eW1      = (const float*)d_in[5];
    const float* eb1      = (const float*)d_in[6];
    const float* eWv      = (const float*)d_in[7];
    const float* ebv      = (const float*)d_in[8];
    const float* eWu      = (const float*)d_in[9];
    const float* ebu      = (const float*)d_in[10];
    const float* ew       = (const float*)d_in[11];
    const float* ebw      = (const float*)d_in[12];
    const float* eW2      = (const float*)d_in[13];
    const float* eb2      = (const float*)d_in[14];
    const float* eWc      = (const float*)d_in[15];
    const float* ebc      = (const float*)d_in[16];
    float* out = (float*)d_out;

    k_zero<<<(B_ * H_ + 255) / 256, 256>>>();
    k_router_gemm<<<dim3(H_ / 64, (B_ * N_) / 64), 256>>>(x, router_W, router_b);
    k_router_head<<<1, 256>>>(fc_W, fc_b, out);
    k_expert_gemm<<<dim3(H_ / 64, N_ / 64, NPAIR), 256>>>(x, eW1, eb1);
    k_scores<<<dim3(N_ / 16, NPAIR), 256>>>(eWv, ebv, eWu, ebu, ew, ebw);
    k_final<<<NPAIR, 256>>>(eW2, eb2, eWc, ebc, out);
}

// round 3
// speedup vs baseline: 1.2298x; 1.2298x over previous
#include <cuda_runtime.h>
#include <math.h>

#define B_ 16
#define N_ 1024
#define D_ 2048
#define E_ 8
#define H_ 512
#define A_ 256
#define L_ 64
#define C_ 8
#define NPAIR 32   // B_ * TOP_K

// ---- scratch (static device globals; no allocation in kernel_launch) ----
__device__ float g_r[B_ * H_];                       // 32 KB  router pooled
__device__ float g_h[(size_t)NPAIR * N_ * H_];       // 64 MB  selected-expert hidden
__device__ float g_scores[NPAIR * N_];               // 128 KB attention scores
__device__ int   g_sel_e[NPAIR];
__device__ float g_sel_w[NPAIR];

// ---------------------------------------------------------------------------
// K0: zero the router accumulator (needed every graph replay)
// ---------------------------------------------------------------------------
__global__ void k_zero() {
    int i = blockIdx.x * blockDim.x + threadIdx.x;
    if (i < B_ * H_) g_r[i] = 0.f;
}

// ---------------------------------------------------------------------------
// Shared 128x128x16 fp32 GEMM tile core. 256 threads, 8x8 micro-tile.
// A row-major [M, D_] (lda = D_), B row-major [D_, H_] (ldb = H_).
// As stored k-major (transposed) so fragment loads are LDS.128.
// Thread (tx=tid&15, ty=tid>>4) owns rows {ty*4+i, 64+ty*4+i} and
// cols {tx*4+j, 64+tx*4+j}  (i,j in 0..3) -> quarter-warp conflict-free.
// ---------------------------------------------------------------------------
__device__ __forceinline__ void gemm_tile_128(
    const float* __restrict__ Abase,   // points at row m0, col 0
    const float* __restrict__ Bbase,   // points at row 0, col n0
    float (&acc)[8][8],
    float (*As)[132], float (*Bs)[128],
    int tid)
{
    const int tx = tid & 15, ty = tid >> 4;
    for (int k0 = 0; k0 < D_; k0 += 16) {
        // load A tile 128x16 -> As[k][m]
        #pragma unroll
        for (int i = 0; i < 2; i++) {
            int f = tid + i * 256;
            int m = f >> 2, q = (f & 3) * 4;
            float4 a4 = *(const float4*)(Abase + (size_t)m * D_ + k0 + q);
            As[q + 0][m] = a4.x; As[q + 1][m] = a4.y;
            As[q + 2][m] = a4.z; As[q + 3][m] = a4.w;
        }
        // load B tile 16x128 -> Bs[k][n]
        #pragma unroll
        for (int i = 0; i < 2; i++) {
            int f = tid + i * 256;
            int kr = f >> 5, n4 = (f & 31) * 4;
            *(float4*)&Bs[kr][n4] =
                *(const float4*)(Bbase + (size_t)(k0 + kr) * H_ + n4);
        }
        __syncthreads();
        #pragma unroll
        for (int kk = 0; kk < 16; kk++) {
            float4 a0 = *(const float4*)&As[kk][ty * 4];
            float4 a1 = *(const float4*)&As[kk][64 + ty * 4];
            float4 b0 = *(const float4*)&Bs[kk][tx * 4];
            float4 b1 = *(const float4*)&Bs[kk][64 + tx * 4];
            float av[8] = {a0.x, a0.y, a0.z, a0.w, a1.x, a1.y, a1.z, a1.w};
            float bv[8] = {b0.x, b0.y, b0.z, b0.w, b1.x, b1.y, b1.z, b1.w};
            #pragma unroll
            for (int i = 0; i < 8; i++)
                #pragma unroll
                for (int j = 0; j < 8; j++)
                    acc[i][j] += av[i] * bv[j];
        }
        __syncthreads();
    }
}

// ---------------------------------------------------------------------------
// K1: router GEMM  r[b,h] += mean_n relu(x[b,n,:] @ router_W[:,h] + rb[h])
// ---------------------------------------------------------------------------
__global__ __launch_bounds__(256, 2) void k_router_gemm(
    const float* __restrict__ X, const float* __restrict__ W,
    const float* __restrict__ rb) {
    __shared__ float As[16][132];
    __shared__ float Bs[16][128];
    const int tid = threadIdx.x;
    const int tx = tid & 15, ty = tid >> 4;
    const int m0 = blockIdx.y * 128;
    const int n0 = blockIdx.x * 128;

    float acc[8][8] = {};
    gemm_tile_128(X + (size_t)m0 * D_, W + n0, acc, As, Bs, tid);

    // relu(+bias), sum this thread's 8 rows per column (all rows same batch)
    float4 bc0 = *(const float4*)(rb + n0 + tx * 4);
    float4 bc1 = *(const float4*)(rb + n0 + 64 + tx * 4);
    float bcv[8] = {bc0.x, bc0.y, bc0.z, bc0.w, bc1.x, bc1.y, bc1.z, bc1.w};
    float colsum[8];
    #pragma unroll
    for (int j = 0; j < 8; j++) {
        float s = 0.f;
        #pragma unroll
        for (int i = 0; i < 8; i++) s += fmaxf(acc[i][j] + bcv[j], 0.f);
        colsum[j] = s;
    }
    float* red = &As[0][0];   // reuse as [16][128]
    #pragma unroll
    for (int j = 0; j < 8; j++) {
        int c = (j < 4) ? (tx * 4 + j) : (64 + tx * 4 + j - 4);
        red[ty * 128 + c] = colsum[j];
    }
    __syncthreads();
    if (tid < 128) {
        float s = 0.f;
        #pragma unroll
        for (int yy = 0; yy < 16; yy++) s += red[yy * 128 + tid];
        int b = m0 / N_;
        atomicAdd(&g_r[b * H_ + n0 + tid], s * (1.f / N_));
    }
}

// ---------------------------------------------------------------------------
// K2: router head: logits = r@fc_W + fc_b, softmax -> g_soft out,
//     top-2 select + renorm weights; zero latent/logits output region.
// ---------------------------------------------------------------------------
__global__ void k_router_head(const float* __restrict__ fcW,
                              const float* __restrict__ fcb,
                              float* __restrict__ out) {
    __shared__ float lg[B_][E_];
    int t = threadIdx.x;
    if (t < B_ * E_) {
        int b = t / E_, e = t % E_;
        float s = fcb[e];
        for (int h = 0; h < H_; h++) s += g_r[b * H_ + h] * fcW[h * E_ + e];
        lg[b][e] = s;
    }
    __syncthreads();
    if (t < B_) {
        int b = t;
        float m = lg[b][0];
        #pragma unroll
        for (int e = 1; e < E_; e++) m = fmaxf(m, lg[b][e]);
        float p[E_]; float s = 0.f;
        #pragma unroll
        for (int e = 0; e < E_; e++) { p[e] = expf(lg[b][e] - m); s += p[e]; }
        float inv = 1.f / s;
        #pragma unroll
        for (int e = 0; e < E_; e++) {
            p[e] *= inv;
            out[B_ * L_ + B_ * C_ + b * E_ + e] = p[e];   // g_soft
        }
        int i0 = 0;
        #pragma unroll
        for (int e = 1; e < E_; e++) if (p[e] > p[i0]) i0 = e;
        int i1 = (i0 == 0) ? 1 : 0;
        #pragma unroll
        for (int e = 0; e < E_; e++) if (e != i1 && e != i0 && p[e] > p[i1]) i1 = e;
        float denom = p[i0] + p[i1] + 1e-8f;
        g_sel_e[2 * b + 0] = i0; g_sel_w[2 * b + 0] = p[i0] / denom;
        g_sel_e[2 * b + 1] = i1; g_sel_w[2 * b + 1] = p[i1] / denom;
    }
    for (int i = t; i < B_ * L_ + B_ * C_; i += blockDim.x) out[i] = 0.f;
}

// ---------------------------------------------------------------------------
// K3: selected-expert hidden GEMM: h = relu(x_b @ eW1[e] + eb1[e])
// ---------------------------------------------------------------------------
__global__ __launch_bounds__(256, 2) void k_expert_gemm(
    const float* __restrict__ X, const float* __restrict__ eW1,
    const float* __restrict__ eb1) {
    __shared__ float As[16][132];
    __shared__ float Bs[16][128];
    const int pair = blockIdx.z;
    const int e = g_sel_e[pair];
    const int b = pair >> 1;
    const int tid = threadIdx.x;
    const int tx = tid & 15, ty = tid >> 4;
    const int m0 = blockIdx.y * 128;
    const int n0 = blockIdx.x * 128;

    float acc[8][8] = {};
    gemm_tile_128(X + (size_t)b * N_ * D_ + (size_t)m0 * D_,
                  eW1 + (size_t)e * D_ * H_ + n0, acc, As, Bs, tid);

    float4 bc0 = *(const float4*)(eb1 + e * H_ + n0 + tx * 4);
    float4 bc1 = *(const float4*)(eb1 + e * H_ + n0 + 64 + tx * 4);
    float* hp = g_h + (size_t)pair * N_ * H_;
    #pragma unroll
    for (int i = 0; i < 8; i++) {
        int r = m0 + ((i < 4) ? (ty * 4 + i) : (64 + ty * 4 + i - 4));
        float4 v0, v1;
        v0.x = fmaxf(acc[i][0] + bc0.x, 0.f);
        v0.y = fmaxf(acc[i][1] + bc0.y, 0.f);
        v0.z = fmaxf(acc[i][2] + bc0.z, 0.f);
        v0.w = fmaxf(acc[i][3] + bc0.w, 0.f);
        v1.x = fmaxf(acc[i][4] + bc1.x, 0.f);
        v1.y = fmaxf(acc[i][5] + bc1.y, 0.f);
        v1.z = fmaxf(acc[i][6] + bc1.z, 0.f);
        v1.w = fmaxf(acc[i][7] + bc1.w, 0.f);
        *(float4*)&hp[(size_t)r * H_ + n0 + tx * 4] = v0;
        *(float4*)&hp[(size_t)r * H_ + n0 + 64 + tx * 4] = v1;
    }
}

// ---------------------------------------------------------------------------
// K4: fused attention scores, 32 n-rows per block (dynamic smem 64 KB).
//   s = sum_a tanh(h.Wv[:,a]+bv) * sigmoid(h.Wu[:,a]+bu) * ew[a]  + ebw
// ---------------------------------------------------------------------------
__global__ __launch_bounds__(256) void k_scores(
    const float* __restrict__ eWv, const float* __restrict__ ebv,
    const float* __restrict__ eWu, const float* __restrict__ ebu,
    const float* __restrict__ ew, const float* __restrict__ ebw) {
    extern __shared__ float hs[];      // [32][H_] = 64 KB
    __shared__ float part[32][8];
    const int pair = blockIdx.y;
    const int n0 = blockIdx.x * 32;
    const int e = g_sel_e[pair];
    const int tid = threadIdx.x;

    const float4* src = (const float4*)(g_h + ((size_t)pair * N_ + n0) * H_);
    float4* dst = (float4*)hs;
    for (int i = tid; i < 32 * H_ / 4; i += 256) dst[i] = src[i];
    __syncthreads();

    const int a = tid;
    const float* Wv = eWv + (size_t)e * H_ * A_ + a;
    const float* Wu = eWu + (size_t)e * H_ * A_ + a;
    float accV[32] = {}, accU[32] = {};
    for (int h = 0; h < H_; h += 2) {
        float wv0 = Wv[(size_t)h * A_],       wu0 = Wu[(size_t)h * A_];
        float wv1 = Wv[(size_t)(h + 1) * A_], wu1 = Wu[(size_t)(h + 1) * A_];
        #pragma unroll
        for (int r = 0; r < 32; r++) {
            float2 hv = *(const float2*)&hs[r * H_ + h];
            accV[r] += hv.x * wv0 + hv.y * wv1;
            accU[r] += hv.x * wu0 + hv.y * wu1;
        }
    }
    const float bv = ebv[e * A_ + a], bu = ebu[e * A_ + a], wgt = ew[e * A_ + a];
    const int lane = tid & 31, warp = tid >> 5;
    #pragma unroll
    for (int r = 0; r < 32; r++) {
        float av = tanhf(accV[r] + bv);
        float au = 1.f / (1.f + expf(-(accU[r] + bu)));
        float v = av * au * wgt;
        v += __shfl_xor_sync(0xffffffffu, v, 16);
        v += __shfl_xor_sync(0xffffffffu, v, 8);
        v += __shfl_xor_sync(0xffffffffu, v, 4);
        v += __shfl_xor_sync(0xffffffffu, v, 2);
        v += __shfl_xor_sync(0xffffffffu, v, 1);
        if (lane == 0) part[r][warp] = v;
    }
    __syncthreads();
    if (tid < 32) {
        float s = ebw[e];
        #pragma unroll
        for (int w = 0; w < 8; w++) s += part[tid][w];
        g_scores[pair * N_ + n0 + tid] = s;
    }
}

// ---------------------------------------------------------------------------
// K5: per pair: softmax over N, pooled = attn^T h, latent/logit heads,
//     weighted atomic combine into d_out.
// ---------------------------------------------------------------------------
__global__ __launch_bounds__(256) void k_final(
    const float* __restrict__ eW2, const float* __restrict__ eb2,
    const float* __restrict__ eWc, const float* __restrict__ ebc,
    float* __restrict__ out) {
    __shared__ float attn[N_];
    __shared__ float red[256];
    __shared__ float pooled[H_];
    __shared__ float lat[L_];
    const int pair = blockIdx.x;
    const int e = g_sel_e[pair], b = pair >> 1;
    const float w = g_sel_w[pair];
    const int t = threadIdx.x;

    const float* sc = g_scores + pair * N_;
    float m = -1e30f;
    for (int i = t; i < N_; i += 256) { float v = sc[i]; attn[i] = v; m = fmaxf(m, v); }
    red[t] = m; __syncthreads();
    for (int s = 128; s > 0; s >>= 1) {
        if (t < s) red[t] = fmaxf(red[t], red[t + s]);
        __syncthreads();
    }
    m = red[0]; __syncthreads();
    float ssum = 0.f;
    for (int i = t; i < N_; i += 256) { float ev = expf(attn[i] - m); attn[i] = ev; ssum += ev; }
    red[t] = ssum; __syncthreads();
    for (int s = 128; s > 0; s >>= 1) {
        if (t < s) red[t] += red[t + s];
        __syncthreads();
    }
    const float inv = 1.f / red[0];

    const float* hp = g_h + (size_t)pair * N_ * H_;
    {
        float acc0 = 0.f, acc1 = 0.f;
        #pragma unroll 8
        for (int n = 0; n < N_; n++) {
            float wn = attn[n];
            acc0 += wn * hp[(size_t)n * H_ + t];
            acc1 += wn * hp[(size_t)n * H_ + t + 256];
        }
        pooled[t] = acc0 * inv;
        pooled[t + 256] = acc1 * inv;
    }
    __syncthreads();
    if (t < L_) {
        float acc = eb2[e * L_ + t];
        for (int h = 0; h < H_; h++) acc += pooled[h] * eW2[((size_t)e * H_ + h) * L_ + t];
        float lv = fmaxf(acc, 0.f);
        lat[t] = lv;
        atomicAdd(&out[b * L_ + t], w * lv);
    }
    __syncthreads();
    if (t < C_) {
        float acc = ebc[e * C_ + t];
        #pragma unroll
        for (int l = 0; l < L_; l++) acc += lat[l] * eWc[((size_t)e * L_ + l) * C_ + t];
        atomicAdd(&out[B_ * L_ + b * C_ + t], w * acc);
    }
}

// ---------------------------------------------------------------------------
extern "C" void kernel_launch(void* const* d_in, const int* in_sizes, int n_in,
                              void* d_out, int out_size) {
    const float* x        = (const float*)d_in[0];
    const float* router_W = (const float*)d_in[1];
    const float* router_b = (const float*)d_in[2];
    const float* fc_W     = (const float*)d_in[3];
    const float* fc_b     = (const float*)d_in[4];
    const float* eW1      = (const float*)d_in[5];
    const float* eb1      = (const float*)d_in[6];
    const float* eWv      = (const float*)d_in[7];
    const float* ebv      = (const float*)d_in[8];
    const float* eWu      = (const float*)d_in[9];
    const float* ebu      = (const float*)d_in[10];
    const float* ew       = (const float*)d_in[11];
    const float* ebw      = (const float*)d_in[12];
    const float* eW2      = (const float*)d_in[13];
    const float* eb2      = (const float*)d_in[14];
    const float* eWc      = (const float*)d_in[15];
    const float* ebc      = (const float*)d_in[16];
    float* out = (float*)d_out;

    static bool attr_done = false;
    if (!attr_done) {
        cudaFuncSetAttribute(k_scores, cudaFuncAttributeMaxDynamicSharedMemorySize,
                             32 * H_ * sizeof(float));
        attr_done = true;
    }

    k_zero<<<(B_ * H_ + 255) / 256, 256>>>();
    k_router_gemm<<<dim3(H_ / 128, (B_ * N_) / 128), 256>>>(x, router_W, router_b);
    k_router_head<<<1, 256>>>(fc_W, fc_b, out);
    k_expert_gemm<<<dim3(H_ / 128, N_ / 128, NPAIR), 256>>>(x, eW1, eb1);
    k_scores<<<dim3(N_ / 32, NPAIR), 256, 32 * H_ * sizeof(float)>>>(
        eWv, ebv, eWu, ebu, ew, ebw);
    k_final<<<NPAIR, 256>>>(eW2, eb2, eWc, ebc, out);
}

// round 6
// speedup vs baseline: 1.9296x; 1.5690x over previous
#include <cuda_runtime.h>
#include <cuda_bf16.h>
#include <math.h>
#include <stdint.h>

#define B_ 16
#define N_ 1024
#define D_ 2048
#define E_ 8
#define H_ 512
#define A_ 256
#define L_ 64
#define C_ 8
#define NPAIR 32   // B_ * TOP_K

// ---- scratch (static device globals; no allocation anywhere) ----
__device__ float g_r[B_ * H_];
__device__ float g_h[(size_t)NPAIR * N_ * H_];         // 64 MB
__device__ float g_scores[NPAIR * N_];
__device__ int   g_sel_e[NPAIR];
__device__ float g_sel_w[NPAIR];
__device__ __nv_bfloat16 g_xhi[(size_t)B_ * N_ * D_];  // 64 MB
__device__ __nv_bfloat16 g_xlo[(size_t)B_ * N_ * D_];  // 64 MB
__device__ __nv_bfloat16 g_w1t_hi[(size_t)E_ * H_ * D_];
__device__ __nv_bfloat16 g_w1t_lo[(size_t)E_ * H_ * D_];
__device__ __nv_bfloat16 g_rwt_hi[(size_t)H_ * D_];
__device__ __nv_bfloat16 g_rwt_lo[(size_t)H_ * D_];

// ======================= base-PTX helpers =======================
__device__ __forceinline__ uint32_t smem_to_u32(const void* p) {
    uint32_t a;
    asm("{ .reg .u64 t; cvta.to.shared.u64 t, %1; cvt.u32.u64 %0, t; }"
        : "=r"(a) : "l"(p));
    return a;
}
__device__ __forceinline__ void cp_async16(uint32_t dst, const void* src) {
    asm volatile("cp.async.ca.shared.global [%0], [%1], 16;"
                 :: "r"(dst), "l"(src) : "memory");
}
#define CP_COMMIT() asm volatile("cp.async.commit_group;" ::: "memory")
#define CP_WAIT1()  asm volatile("cp.async.wait_group 1;" ::: "memory")

__device__ __forceinline__ uint32_t lds32(uint32_t addr) {
    uint32_t v;
    asm volatile("ld.shared.b32 %0, [%1];" : "=r"(v) : "r"(addr));
    return v;
}
__device__ __forceinline__ void mma_bf16(float* c, const uint32_t* a,
                                         const uint32_t* b) {
    asm volatile(
        "mma.sync.aligned.m16n8k16.row.col.f32.bf16.bf16.f32 "
        "{%0,%1,%2,%3}, {%4,%5,%6,%7}, {%8,%9}, {%0,%1,%2,%3};"
        : "+f"(c[0]), "+f"(c[1]), "+f"(c[2]), "+f"(c[3])
        : "r"(a[0]), "r"(a[1]), "r"(a[2]), "r"(a[3]),
          "r"(b[0]), "r"(b[1]));
}

// ======================= conversion kernels =======================
__global__ __launch_bounds__(256) void k_conv_x(const float* __restrict__ x) {
    size_t i = ((size_t)blockIdx.x * 256 + threadIdx.x) * 4;
    float4 v = *(const float4*)(x + i);
    __nv_bfloat16 h0 = __float2bfloat16(v.x), h1 = __float2bfloat16(v.y);
    __nv_bfloat16 h2 = __float2bfloat16(v.z), h3 = __float2bfloat16(v.w);
    __nv_bfloat16 l0 = __float2bfloat16(v.x - __bfloat162float(h0));
    __nv_bfloat16 l1 = __float2bfloat16(v.y - __bfloat162float(h1));
    __nv_bfloat16 l2 = __float2bfloat16(v.z - __bfloat162float(h2));
    __nv_bfloat16 l3 = __float2bfloat16(v.w - __bfloat162float(h3));
    *(__nv_bfloat162*)(g_xhi + i)     = __nv_bfloat162(h0, h1);
    *(__nv_bfloat162*)(g_xhi + i + 2) = __nv_bfloat162(h2, h3);
    *(__nv_bfloat162*)(g_xlo + i)     = __nv_bfloat162(l0, l1);
    *(__nv_bfloat162*)(g_xlo + i + 2) = __nv_bfloat162(l2, l3);
}

// transpose + split weights: src [D_,H_] row-major -> dst [H_,D_] (K-major)
__global__ void k_conv_w(const float* __restrict__ routerW,
                         const float* __restrict__ eW1) {
    __shared__ float t[32][33];
    const int z = blockIdx.z;
    const float* src = z ? (eW1 + (size_t)(z - 1) * D_ * H_) : routerW;
    __nv_bfloat16* dh = z ? (g_w1t_hi + (size_t)(z - 1) * H_ * D_) : g_rwt_hi;
    __nv_bfloat16* dl = z ? (g_w1t_lo + (size_t)(z - 1) * H_ * D_) : g_rwt_lo;
    const int k0 = blockIdx.x * 32, n0 = blockIdx.y * 32;
    #pragma unroll
    for (int i = 0; i < 4; i++) {
        int k = k0 + threadIdx.y + i * 8;
        t[threadIdx.y + i * 8][threadIdx.x] = src[(size_t)k * H_ + n0 + threadIdx.x];
    }
    __syncthreads();
    #pragma unroll
    for (int i = 0; i < 4; i++) {
        int n = n0 + threadIdx.y + i * 8;
        float v = t[threadIdx.x][threadIdx.y + i * 8];
        __nv_bfloat16 hv = __float2bfloat16(v);
        __nv_bfloat16 lv = __float2bfloat16(v - __bfloat162float(hv));
        dh[(size_t)n * D_ + k0 + threadIdx.x] = hv;
        dl[(size_t)n * D_ + k0 + threadIdx.x] = lv;
    }
}

// ======================= mma.sync GEMM core =======================
// Block tile 128x128, K-chunks of 32 bf16. 8 warps, warp tile 32x64.
// smem per stage: 4 arrays (Ah, Al, Bh, Bl), each 128 rows x 80 B (32 bf16 + pad)
#define ROWB   80
#define ARRB   (128 * ROWB)     // 10240
#define STAGEB (4 * ARRB)       // 40960
#define NSTG   3
#define MM_SMEM (NSTG * STAGEB) // 122880
#define NCHUNK (D_ / 32)        // 64

__device__ __forceinline__ void mm_load_stage(
    uint32_t sb, int stg, int k0, int tid,
    const __nv_bfloat16* Ah, const __nv_bfloat16* Al,
    const __nv_bfloat16* Bh, const __nv_bfloat16* Bl) {
    const __nv_bfloat16* ps[4] = {Ah, Al, Bh, Bl};
    uint32_t base = sb + stg * STAGEB;
    int row0 = tid >> 2, c16 = tid & 3;
    #pragma unroll
    for (int arr = 0; arr < 4; arr++) {
        #pragma unroll
        for (int half = 0; half < 2; half++) {
            int row = row0 + half * 64;
            cp_async16(base + arr * ARRB + row * ROWB + c16 * 16,
                       ps[arr] + (size_t)row * D_ + k0 + c16 * 8);
        }
    }
}

__device__ __forceinline__ void mm_core(
    const __nv_bfloat16* __restrict__ Ah, const __nv_bfloat16* __restrict__ Al,
    const __nv_bfloat16* __restrict__ Bh, const __nv_bfloat16* __restrict__ Bl,
    uint32_t sb, int tid, float acc[2][8][4]) {
    const int lane = tid & 31, wid = tid >> 5;
    const int wm = wid & 3, wn = wid >> 2;
    const int l4 = lane >> 2, q2 = (lane & 3) * 2;

    mm_load_stage(sb, 0, 0, tid, Ah, Al, Bh, Bl);  CP_COMMIT();
    mm_load_stage(sb, 1, 32, tid, Ah, Al, Bh, Bl); CP_COMMIT();

    for (int s = 0; s < NCHUNK; s++) {
        CP_WAIT1();
        __syncthreads();
        if (s + 2 < NCHUNK)
            mm_load_stage(sb, (s + 2) % NSTG, (s + 2) * 32, tid, Ah, Al, Bh, Bl);
        CP_COMMIT();

        const uint32_t b0 = sb + (s % NSTG) * STAGEB;
        #pragma unroll
        for (int ks = 0; ks < 32; ks += 16) {
            uint32_t ah[2][4], al[2][4], bh[8][2], bl[8][2];
            #pragma unroll
            for (int mt = 0; mt < 2; mt++) {
                uint32_t r0 = b0 + (wm * 32 + mt * 16 + l4) * ROWB + (ks + q2) * 2;
                ah[mt][0] = lds32(r0);
                ah[mt][1] = lds32(r0 + 8 * ROWB);
                ah[mt][2] = lds32(r0 + 16);
                ah[mt][3] = lds32(r0 + 8 * ROWB + 16);
                uint32_t r1 = r0 + ARRB;
                al[mt][0] = lds32(r1);
                al[mt][1] = lds32(r1 + 8 * ROWB);
                al[mt][2] = lds32(r1 + 16);
                al[mt][3] = lds32(r1 + 8 * ROWB + 16);
            }
            #pragma unroll
            for (int nt = 0; nt < 8; nt++) {
                uint32_t r0 = b0 + 2 * ARRB + (wn * 64 + nt * 8 + l4) * ROWB + (ks + q2) * 2;
                bh[nt][0] = lds32(r0);
                bh[nt][1] = lds32(r0 + 16);
                uint32_t r1 = r0 + ARRB;
                bl[nt][0] = lds32(r1);
                bl[nt][1] = lds32(r1 + 16);
            }
            // term-major ordering: same-acc MMAs spaced 16 apart
            #pragma unroll
            for (int mt = 0; mt < 2; mt++)
                #pragma unroll
                for (int nt = 0; nt < 8; nt++)
                    mma_bf16(acc[mt][nt], ah[mt], bh[nt]);
            #pragma unroll
            for (int mt = 0; mt < 2; mt++)
                #pragma unroll
                for (int nt = 0; nt < 8; nt++)
                    mma_bf16(acc[mt][nt], al[mt], bh[nt]);
            #pragma unroll
            for (int mt = 0; mt < 2; mt++)
                #pragma unroll
                for (int nt = 0; nt < 8; nt++)
                    mma_bf16(acc[mt][nt], ah[mt], bl[nt]);
        }
    }
}

// ---------------------------------------------------------------------------
// K1: router GEMM (mma.sync): relu(x@W + b), mean over N -> atomic into g_r
// grid (H_/128=4, B_*N_/128=128)
// ---------------------------------------------------------------------------
__global__ __launch_bounds__(256) void k_mm_router(const float* __restrict__ rb) {
    extern __shared__ char smem[];
    const uint32_t sb = smem_to_u32(smem);
    const int tid = threadIdx.x;
    const int n0 = blockIdx.x * 128, m0 = blockIdx.y * 128;

    float acc[2][8][4] = {};
    mm_core(g_xhi + (size_t)m0 * D_, g_xlo + (size_t)m0 * D_,
            g_rwt_hi + (size_t)n0 * D_, g_rwt_lo + (size_t)n0 * D_,
            sb, tid, acc);

    const int lane = tid & 31, wid = tid >> 5;
    const int wm = wid & 3, wn = wid >> 2;  (void)wm;
    const int l4 = lane >> 2, q2 = (lane & 3) * 2;
    const int b = m0 / N_;
    #pragma unroll
    for (int nt = 0; nt < 8; nt++) {
        int col = n0 + wn * 64 + nt * 8 + q2;
        float bx = rb[col], by = rb[col + 1];
        float s0 = 0.f, s1 = 0.f;
        #pragma unroll
        for (int mt = 0; mt < 2; mt++) {
            s0 += fmaxf(acc[mt][nt][0] + bx, 0.f) + fmaxf(acc[mt][nt][2] + bx, 0.f);
            s1 += fmaxf(acc[mt][nt][1] + by, 0.f) + fmaxf(acc[mt][nt][3] + by, 0.f);
        }
        s0 += __shfl_xor_sync(0xffffffffu, s0, 4);
        s0 += __shfl_xor_sync(0xffffffffu, s0, 8);
        s0 += __shfl_xor_sync(0xffffffffu, s0, 16);
        s1 += __shfl_xor_sync(0xffffffffu, s1, 4);
        s1 += __shfl_xor_sync(0xffffffffu, s1, 8);
        s1 += __shfl_xor_sync(0xffffffffu, s1, 16);
        if (l4 == 0) {
            atomicAdd(&g_r[b * H_ + col],     s0 * (1.f / N_));
            atomicAdd(&g_r[b * H_ + col + 1], s1 * (1.f / N_));
        }
    }
}

// ---------------------------------------------------------------------------
// K3: expert GEMM (mma.sync): h = relu(x_b @ eW1[e] + eb1[e]) for top-2 pairs
// grid (H_/128=4, N_/128=8, NPAIR)
// ---------------------------------------------------------------------------
__global__ __launch_bounds__(256) void k_mm_expert(const float* __restrict__ eb1) {
    extern __shared__ char smem[];
    const uint32_t sb = smem_to_u32(smem);
    const int tid = threadIdx.x;
    const int pair = blockIdx.z;
    const int e = g_sel_e[pair], b = pair >> 1;
    const int n0 = blockIdx.x * 128, m0 = blockIdx.y * 128;

    float acc[2][8][4] = {};
    mm_core(g_xhi + ((size_t)b * N_ + m0) * D_, g_xlo + ((size_t)b * N_ + m0) * D_,
            g_w1t_hi + ((size_t)e * H_ + n0) * D_,
            g_w1t_lo + ((size_t)e * H_ + n0) * D_, sb, tid, acc);

    const int lane = tid & 31, wid = tid >> 5;
    const int wm = wid & 3, wn = wid >> 2;
    const int l4 = lane >> 2, q2 = (lane & 3) * 2;
    float* hp = g_h + (size_t)pair * N_ * H_;
    #pragma unroll
    for (int mt = 0; mt < 2; mt++) {
        int row = m0 + wm * 32 + mt * 16 + l4;
        #pragma unroll
        for (int nt = 0; nt < 8; nt++) {
            int col = n0 + wn * 64 + nt * 8 + q2;
            float bx = eb1[e * H_ + col], by = eb1[e * H_ + col + 1];
            float2 v0, v1;
            v0.x = fmaxf(acc[mt][nt][0] + bx, 0.f);
            v0.y = fmaxf(acc[mt][nt][1] + by, 0.f);
            v1.x = fmaxf(acc[mt][nt][2] + bx, 0.f);
            v1.y = fmaxf(acc[mt][nt][3] + by, 0.f);
            *(float2*)&hp[(size_t)row * H_ + col] = v0;
            *(float2*)&hp[(size_t)(row + 8) * H_ + col] = v1;
        }
    }
}

// ======================= unchanged kernels =======================
__global__ void k_zero() {
    int i = blockIdx.x * blockDim.x + threadIdx.x;
    if (i < B_ * H_) g_r[i] = 0.f;
}

__global__ void k_router_head(const float* __restrict__ fcW,
                              const float* __restrict__ fcb,
                              float* __restrict__ out) {
    __shared__ float lg[B_][E_];
    int t = threadIdx.x;
    if (t < B_ * E_) {
        int b = t / E_, e = t % E_;
        float s = fcb[e];
        for (int h = 0; h < H_; h++) s += g_r[b * H_ + h] * fcW[h * E_ + e];
        lg[b][e] = s;
    }
    __syncthreads();
    if (t < B_) {
        int b = t;
        float m = lg[b][0];
        #pragma unroll
        for (int e = 1; e < E_; e++) m = fmaxf(m, lg[b][e]);
        float p[E_]; float s = 0.f;
        #pragma unroll
        for (int e = 0; e < E_; e++) { p[e] = expf(lg[b][e] - m); s += p[e]; }
        float inv = 1.f / s;
        #pragma unroll
        for (int e = 0; e < E_; e++) {
            p[e] *= inv;
            out[B_ * L_ + B_ * C_ + b * E_ + e] = p[e];
        }
        int i0 = 0;
        #pragma unroll
        for (int e = 1; e < E_; e++) if (p[e] > p[i0]) i0 = e;
        int i1 = (i0 == 0) ? 1 : 0;
        #pragma unroll
        for (int e = 0; e < E_; e++) if (e != i1 && e != i0 && p[e] > p[i1]) i1 = e;
        float denom = p[i0] + p[i1] + 1e-8f;
        g_sel_e[2 * b + 0] = i0; g_sel_w[2 * b + 0] = p[i0] / denom;
        g_sel_e[2 * b + 1] = i1; g_sel_w[2 * b + 1] = p[i1] / denom;
    }
    for (int i = t; i < B_ * L_ + B_ * C_; i += blockDim.x) out[i] = 0.f;
}

__global__ __launch_bounds__(256) void k_scores(
    const float* __restrict__ eWv, const float* __restrict__ ebv,
    const float* __restrict__ eWu, const float* __restrict__ ebu,
    const float* __restrict__ ew, const float* __restrict__ ebw) {
    extern __shared__ float hs[];      // [32][H_] = 64 KB
    __shared__ float part[32][8];
    const int pair = blockIdx.y;
    const int n0 = blockIdx.x * 32;
    const int e = g_sel_e[pair];
    const int tid = threadIdx.x;

    const float4* src = (const float4*)(g_h + ((size_t)pair * N_ + n0) * H_);
    float4* dst = (float4*)hs;
    for (int i = tid; i < 32 * H_ / 4; i += 256) dst[i] = src[i];
    __syncthreads();

    const int a = tid;
    const float* Wv = eWv + (size_t)e * H_ * A_ + a;
    const float* Wu = eWu + (size_t)e * H_ * A_ + a;
    float accV[32] = {}, accU[32] = {};
    for (int h = 0; h < H_; h += 2) {
        float wv0 = Wv[(size_t)h * A_],       wu0 = Wu[(size_t)h * A_];
        float wv1 = Wv[(size_t)(h + 1) * A_], wu1 = Wu[(size_t)(h + 1) * A_];
        #pragma unroll
        for (int r = 0; r < 32; r++) {
            float2 hv = *(const float2*)&hs[r * H_ + h];
            accV[r] += hv.x * wv0 + hv.y * wv1;
            accU[r] += hv.x * wu0 + hv.y * wu1;
        }
    }
    const float bv = ebv[e * A_ + a], bu = ebu[e * A_ + a], wgt = ew[e * A_ + a];
    const int lane = tid & 31, warp = tid >> 5;
    #pragma unroll
    for (int r = 0; r < 32; r++) {
        float av = tanhf(accV[r] + bv);
        float au = 1.f / (1.f + expf(-(accU[r] + bu)));
        float v = av * au * wgt;
        v += __shfl_xor_sync(0xffffffffu, v, 16);
        v += __shfl_xor_sync(0xffffffffu, v, 8);
        v += __shfl_xor_sync(0xffffffffu, v, 4);
        v += __shfl_xor_sync(0xffffffffu, v, 2);
        v += __shfl_xor_sync(0xffffffffu, v, 1);
        if (lane == 0) part[r][warp] = v;
    }
    __syncthreads();
    if (tid < 32) {
        float s = ebw[e];
        #pragma unroll
        for (int w = 0; w < 8; w++) s += part[tid][w];
        g_scores[pair * N_ + n0 + tid] = s;
    }
}

__global__ __launch_bounds__(256) void k_final(
    const float* __restrict__ eW2, const float* __restrict__ eb2,
    const float* __restrict__ eWc, const float* __restrict__ ebc,
    float* __restrict__ out) {
    __shared__ float attn[N_];
    __shared__ float red[256];
    __shared__ float pooled[H_];
    __shared__ float lat[L_];
    const int pair = blockIdx.x;
    const int e = g_sel_e[pair], b = pair >> 1;
    const float w = g_sel_w[pair];
    const int t = threadIdx.x;

    const float* sc = g_scores + pair * N_;
    float m = -1e30f;
    for (int i = t; i < N_; i += 256) { float v = sc[i]; attn[i] = v; m = fmaxf(m, v); }
    red[t] = m; __syncthreads();
    for (int s = 128; s > 0; s >>= 1) {
        if (t < s) red[t] = fmaxf(red[t], red[t + s]);
        __syncthreads();
    }
    m = red[0]; __syncthreads();
    float ssum = 0.f;
    for (int i = t; i < N_; i += 256) { float ev = expf(attn[i] - m); attn[i] = ev; ssum += ev; }
    red[t] = ssum; __syncthreads();
    for (int s = 128; s > 0; s >>= 1) {
        if (t < s) red[t] += red[t + s];
        __syncthreads();
    }
    const float inv = 1.f / red[0];

    const float* hp = g_h + (size_t)pair * N_ * H_;
    {
        float acc0 = 0.f, acc1 = 0.f;
        #pragma unroll 8
        for (int n = 0; n < N_; n++) {
            float wn = attn[n];
            acc0 += wn * hp[(size_t)n * H_ + t];
            acc1 += wn * hp[(size_t)n * H_ + t + 256];
        }
        pooled[t] = acc0 * inv;
        pooled[t + 256] = acc1 * inv;
    }
    __syncthreads();
    if (t < L_) {
        float acc = eb2[e * L_ + t];
        for (int h = 0; h < H_; h++) acc += pooled[h] * eW2[((size_t)e * H_ + h) * L_ + t];
        float lv = fmaxf(acc, 0.f);
        lat[t] = lv;
        atomicAdd(&out[b * L_ + t], w * lv);
    }
    __syncthreads();
    if (t < C_) {
        float acc = ebc[e * C_ + t];
        #pragma unroll
        for (int l = 0; l < L_; l++) acc += lat[l] * eWc[((size_t)e * L_ + l) * C_ + t];
        atomicAdd(&out[B_ * L_ + b * C_ + t], w * acc);
    }
}

// ---------------------------------------------------------------------------
extern "C" void kernel_launch(void* const* d_in, const int* in_sizes, int n_in,
                              void* d_out, int out_size) {
    const float* x        = (const float*)d_in[0];
    const float* router_W = (const float*)d_in[1];
    const float* router_b = (const float*)d_in[2];
    const float* fc_W     = (const float*)d_in[3];
    const float* fc_b     = (const float*)d_in[4];
    const float* eW1      = (const float*)d_in[5];
    const float* eb1      = (const float*)d_in[6];
    const float* eWv      = (const float*)d_in[7];
    const float* ebv      = (const float*)d_in[8];
    const float* eWu      = (const float*)d_in[9];
    const float* ebu      = (const float*)d_in[10];
    const float* ew       = (const float*)d_in[11];
    const float* ebw      = (const float*)d_in[12];
    const float* eW2      = (const float*)d_in[13];
    const float* eb2      = (const float*)d_in[14];
    const float* eWc      = (const float*)d_in[15];
    const float* ebc      = (const float*)d_in[16];
    float* out = (float*)d_out;

    static bool attr_done = false;
    if (!attr_done) {
        cudaFuncSetAttribute(k_scores, cudaFuncAttributeMaxDynamicSharedMemorySize,
                             32 * H_ * sizeof(float));
        cudaFuncSetAttribute(k_mm_router, cudaFuncAttributeMaxDynamicSharedMemorySize,
                             MM_SMEM);
        cudaFuncSetAttribute(k_mm_expert, cudaFuncAttributeMaxDynamicSharedMemorySize,
                             MM_SMEM);
        attr_done = true;
    }

    k_conv_x<<<(B_ * N_ * D_) / 1024, 256>>>(x);
    k_conv_w<<<dim3(D_ / 32, H_ / 32, E_ + 1), dim3(32, 8)>>>(router_W, eW1);
    k_zero<<<(B_ * H_ + 255) / 256, 256>>>();
    k_mm_router<<<dim3(H_ / 128, (B_ * N_) / 128), 256, MM_SMEM>>>(router_b);
    k_router_head<<<1, 256>>>(fc_W, fc_b, out);
    k_mm_expert<<<dim3(H_ / 128, N_ / 128, NPAIR), 256, MM_SMEM>>>(eb1);
    k_scores<<<dim3(N_ / 32, NPAIR), 256, 32 * H_ * sizeof(float)>>>(
        eWv, ebv, eWu, ebu, ew, ebw);
    k_final<<<NPAIR, 256>>>(eW2, eb2, eWc, ebc, out);
}

// round 11
// speedup vs baseline: 2.1310x; 1.1044x over previous
#include <cuda_runtime.h>
#include <cuda_bf16.h>
#include <math.h>
#include <stdint.h>

#define B_ 16
#define N_ 1024
#define D_ 2048
#define E_ 8
#define H_ 512
#define A_ 256
#define L_ 64
#define C_ 8
#define NPAIR 32   // B_ * TOP_K

// ---- scratch (static device globals; no allocation anywhere) ----
__device__ float g_r[B_ * H_];
__device__ float g_h[(size_t)NPAIR * N_ * H_];         // 64 MB
__device__ float g_scores[NPAIR * N_];
__device__ float g_pooled[NPAIR * H_];
__device__ int   g_sel_e[NPAIR];
__device__ float g_sel_w[NPAIR];
__device__ __nv_bfloat16 g_xhi[(size_t)B_ * N_ * D_];  // 64 MB
__device__ __nv_bfloat16 g_xlo[(size_t)B_ * N_ * D_];  // 64 MB
__device__ __nv_bfloat16 g_w1t_hi[(size_t)E_ * H_ * D_];
__device__ __nv_bfloat16 g_w1t_lo[(size_t)E_ * H_ * D_];
__device__ __nv_bfloat16 g_rwt_hi[(size_t)H_ * D_];
__device__ __nv_bfloat16 g_rwt_lo[(size_t)H_ * D_];

// ======================= base-PTX helpers =======================
__device__ __forceinline__ uint32_t smem_to_u32(const void* p) {
    uint32_t a;
    asm("{ .reg .u64 t; cvta.to.shared.u64 t, %1; cvt.u32.u64 %0, t; }"
        : "=r"(a) : "l"(p));
    return a;
}
__device__ __forceinline__ void cp_async16(uint32_t dst, const void* src) {
    asm volatile("cp.async.ca.shared.global [%0], [%1], 16;"
                 :: "r"(dst), "l"(src) : "memory");
}
#define CP_COMMIT() asm volatile("cp.async.commit_group;" ::: "memory")
#define CP_WAIT1()  asm volatile("cp.async.wait_group 1;" ::: "memory")

__device__ __forceinline__ void ldmx4(uint32_t* r, uint32_t addr) {
    asm volatile("ldmatrix.sync.aligned.m8n8.x4.shared.b16 {%0,%1,%2,%3}, [%4];"
        : "=r"(r[0]), "=r"(r[1]), "=r"(r[2]), "=r"(r[3]) : "r"(addr));
}
__device__ __forceinline__ void mma_bf16(float* c, const uint32_t* a,
                                         const uint32_t* b) {
    asm volatile(
        "mma.sync.aligned.m16n8k16.row.col.f32.bf16.bf16.f32 "
        "{%0,%1,%2,%3}, {%4,%5,%6,%7}, {%8,%9}, {%0,%1,%2,%3};"
        : "+f"(c[0]), "+f"(c[1]), "+f"(c[2]), "+f"(c[3])
        : "r"(a[0]), "r"(a[1]), "r"(a[2]), "r"(a[3]),
          "r"(b[0]), "r"(b[1]));
}

// ======================= conversion kernels =======================
__global__ __launch_bounds__(256) void k_conv_x(const float* __restrict__ x) {
    size_t i = ((size_t)blockIdx.x * 256 + threadIdx.x) * 4;
    float4 v = *(const float4*)(x + i);
    __nv_bfloat16 h0 = __float2bfloat16(v.x), h1 = __float2bfloat16(v.y);
    __nv_bfloat16 h2 = __float2bfloat16(v.z), h3 = __float2bfloat16(v.w);
    __nv_bfloat16 l0 = __float2bfloat16(v.x - __bfloat162float(h0));
    __nv_bfloat16 l1 = __float2bfloat16(v.y - __bfloat162float(h1));
    __nv_bfloat16 l2 = __float2bfloat16(v.z - __bfloat162float(h2));
    __nv_bfloat16 l3 = __float2bfloat16(v.w - __bfloat162float(h3));
    *(__nv_bfloat162*)(g_xhi + i)     = __nv_bfloat162(h0, h1);
    *(__nv_bfloat162*)(g_xhi + i + 2) = __nv_bfloat162(h2, h3);
    *(__nv_bfloat162*)(g_xlo + i)     = __nv_bfloat162(l0, l1);
    *(__nv_bfloat162*)(g_xlo + i + 2) = __nv_bfloat162(l2, l3);
}

// transpose + split weights: src [D_,H_] row-major -> dst [H_,D_] (K-major)
__global__ void k_conv_w(const float* __restrict__ routerW,
                         const float* __restrict__ eW1) {
    __shared__ float t[32][33];
    const int z = blockIdx.z;
    const float* src = z ? (eW1 + (size_t)(z - 1) * D_ * H_) : routerW;
    __nv_bfloat16* dh = z ? (g_w1t_hi + (size_t)(z - 1) * H_ * D_) : g_rwt_hi;
    __nv_bfloat16* dl = z ? (g_w1t_lo + (size_t)(z - 1) * H_ * D_) : g_rwt_lo;
    const int k0 = blockIdx.x * 32, n0 = blockIdx.y * 32;
    #pragma unroll
    for (int i = 0; i < 4; i++) {
        int k = k0 + threadIdx.y + i * 8;
        t[threadIdx.y + i * 8][threadIdx.x] = src[(size_t)k * H_ + n0 + threadIdx.x];
    }
    __syncthreads();
    #pragma unroll
    for (int i = 0; i < 4; i++) {
        int n = n0 + threadIdx.y + i * 8;
        float v = t[threadIdx.x][threadIdx.y + i * 8];
        __nv_bfloat16 hv = __float2bfloat16(v);
        __nv_bfloat16 lv = __float2bfloat16(v - __bfloat162float(hv));
        dh[(size_t)n * D_ + k0 + threadIdx.x] = hv;
        dl[(size_t)n * D_ + k0 + threadIdx.x] = lv;
    }
}

// ======================= mma.sync GEMM core =======================
// Block tile 128x128, K-chunks of 32 bf16. 8 warps, warp tile 32x64.
// 2-stage cp.async pipeline; ldmatrix fragment loads.
#define ROWB   80
#define ARRB   (128 * ROWB)     // 10240
#define STAGEB (4 * ARRB)       // 40960
#define MM_SMEM (2 * STAGEB)    // 81920 -> 2 CTAs/SM
#define NCHUNK (D_ / 32)        // 64

__device__ __forceinline__ void mm_load_stage(
    uint32_t sb, int stg, int k0, int tid,
    const __nv_bfloat16* Ah, const __nv_bfloat16* Al,
    const __nv_bfloat16* Bh, const __nv_bfloat16* Bl) {
    const __nv_bfloat16* ps[4] = {Ah, Al, Bh, Bl};
    uint32_t base = sb + stg * STAGEB;
    int row0 = tid >> 2, c16 = tid & 3;
    #pragma unroll
    for (int arr = 0; arr < 4; arr++) {
        #pragma unroll
        for (int half = 0; half < 2; half++) {
            int row = row0 + half * 64;
            cp_async16(base + arr * ARRB + row * ROWB + c16 * 16,
                       ps[arr] + (size_t)row * D_ + k0 + c16 * 8);
        }
    }
}

__device__ __forceinline__ void mm_core(
    const __nv_bfloat16* __restrict__ Ah, const __nv_bfloat16* __restrict__ Al,
    const __nv_bfloat16* __restrict__ Bh, const __nv_bfloat16* __restrict__ Bl,
    uint32_t sb, int tid, float acc[2][8][4]) {
    const int lane = tid & 31, wid = tid >> 5;
    const int wm = wid & 3, wn = wid >> 2;

    mm_load_stage(sb, 0, 0, tid, Ah, Al, Bh, Bl);  CP_COMMIT();
    mm_load_stage(sb, 1, 32, tid, Ah, Al, Bh, Bl); CP_COMMIT();

    // ldmatrix lane-address components (constant across chunks)
    const int a_row = lane & 15, a_kb = (lane >> 4) * 16;          // bytes
    const int b_row = ((lane >> 4) & 1) * 8 + (lane & 7);
    const int b_kb = ((lane >> 3) & 1) * 16;                       // bytes

    for (int s = 0; s < NCHUNK; s++) {
        CP_WAIT1();
        __syncthreads();
        const uint32_t b0 = sb + (s & 1) * STAGEB;
        #pragma unroll
        for (int ks = 0; ks < 2; ks++) {       // two k16 slices (byte off 0/32)
            uint32_t ah[2][4], al[2][4], bh[8][2], bl[8][2];
            #pragma unroll
            for (int mt = 0; mt < 2; mt++) {
                uint32_t ra = b0 + (wm * 32 + mt * 16 + a_row) * ROWB + ks * 32 + a_kb;
                ldmx4(ah[mt], ra);
                ldmx4(al[mt], ra + ARRB);
            }
            #pragma unroll
            for (int np = 0; np < 4; np++) {
                uint32_t rb = b0 + 2 * ARRB +
                    (wn * 64 + np * 16 + b_row) * ROWB + ks * 32 + b_kb;
                ldmx4(&bh[2 * np][0], rb);
                ldmx4(&bl[2 * np][0], rb + ARRB);
            }
            // term-major: same-acc MMAs spaced 16 apart
            #pragma unroll
            for (int mt = 0; mt < 2; mt++)
                #pragma unroll
                for (int nt = 0; nt < 8; nt++)
                    mma_bf16(acc[mt][nt], ah[mt], bh[nt]);
            #pragma unroll
            for (int mt = 0; mt < 2; mt++)
                #pragma unroll
                for (int nt = 0; nt < 8; nt++)
                    mma_bf16(acc[mt][nt], al[mt], bh[nt]);
            #pragma unroll
            for (int mt = 0; mt < 2; mt++)
                #pragma unroll
                for (int nt = 0; nt < 8; nt++)
                    mma_bf16(acc[mt][nt], ah[mt], bl[nt]);
        }
        __syncthreads();
        if (s + 2 < NCHUNK)
            mm_load_stage(sb, s & 1, (s + 2) * 32, tid, Ah, Al, Bh, Bl);
        CP_COMMIT();
    }
}

// ---------------------------------------------------------------------------
// K1: router GEMM: relu(x@W + b), mean over N -> atomic into g_r
// ---------------------------------------------------------------------------
__global__ __launch_bounds__(256, 2) void k_mm_router(const float* __restrict__ rb) {
    extern __shared__ char smem[];
    const uint32_t sb = smem_to_u32(smem);
    const int tid = threadIdx.x;
    const int n0 = blockIdx.x * 128, m0 = blockIdx.y * 128;

    float acc[2][8][4] = {};
    mm_core(g_xhi + (size_t)m0 * D_, g_xlo + (size_t)m0 * D_,
            g_rwt_hi + (size_t)n0 * D_, g_rwt_lo + (size_t)n0 * D_,
            sb, tid, acc);

    const int lane = tid & 31, wid = tid >> 5;
    const int wn = wid >> 2;
    const int l4 = lane >> 2, q2 = (lane & 3) * 2;
    const int b = m0 / N_;
    #pragma unroll
    for (int nt = 0; nt < 8; nt++) {
        int col = n0 + wn * 64 + nt * 8 + q2;
        float bx = rb[col], by = rb[col + 1];
        float s0 = 0.f, s1 = 0.f;
        #pragma unroll
        for (int mt = 0; mt < 2; mt++) {
            s0 += fmaxf(acc[mt][nt][0] + bx, 0.f) + fmaxf(acc[mt][nt][2] + bx, 0.f);
            s1 += fmaxf(acc[mt][nt][1] + by, 0.f) + fmaxf(acc[mt][nt][3] + by, 0.f);
        }
        s0 += __shfl_xor_sync(0xffffffffu, s0, 4);
        s0 += __shfl_xor_sync(0xffffffffu, s0, 8);
        s0 += __shfl_xor_sync(0xffffffffu, s0, 16);
        s1 += __shfl_xor_sync(0xffffffffu, s1, 4);
        s1 += __shfl_xor_sync(0xffffffffu, s1, 8);
        s1 += __shfl_xor_sync(0xffffffffu, s1, 16);
        if (l4 == 0) {
            atomicAdd(&g_r[b * H_ + col],     s0 * (1.f / N_));
            atomicAdd(&g_r[b * H_ + col + 1], s1 * (1.f / N_));
        }
    }
}

// ---------------------------------------------------------------------------
// K3: expert GEMM: h = relu(x_b @ eW1[e] + eb1[e]) for top-2 pairs
// ---------------------------------------------------------------------------
__global__ __launch_bounds__(256, 2) void k_mm_expert(const float* __restrict__ eb1) {
    extern __shared__ char smem[];
    const uint32_t sb = smem_to_u32(smem);
    const int tid = threadIdx.x;
    const int pair = blockIdx.z;
    const int e = g_sel_e[pair], b = pair >> 1;
    const int n0 = blockIdx.x * 128, m0 = blockIdx.y * 128;

    float acc[2][8][4] = {};
    mm_core(g_xhi + ((size_t)b * N_ + m0) * D_, g_xlo + ((size_t)b * N_ + m0) * D_,
            g_w1t_hi + ((size_t)e * H_ + n0) * D_,
            g_w1t_lo + ((size_t)e * H_ + n0) * D_, sb, tid, acc);

    const int lane = tid & 31, wid = tid >> 5;
    const int wm = wid & 3, wn = wid >> 2;
    const int l4 = lane >> 2, q2 = (lane & 3) * 2;
    float* hp = g_h + (size_t)pair * N_ * H_;
    #pragma unroll
    for (int mt = 0; mt < 2; mt++) {
        int row = m0 + wm * 32 + mt * 16 + l4;
        #pragma unroll
        for (int nt = 0; nt < 8; nt++) {
            int col = n0 + wn * 64 + nt * 8 + q2;
            float bx = eb1[e * H_ + col], by = eb1[e * H_ + col + 1];
            float2 v0, v1;
            v0.x = fmaxf(acc[mt][nt][0] + bx, 0.f);
            v0.y = fmaxf(acc[mt][nt][1] + by, 0.f);
            v1.x = fmaxf(acc[mt][nt][2] + bx, 0.f);
            v1.y = fmaxf(acc[mt][nt][3] + by, 0.f);
            *(float2*)&hp[(size_t)row * H_ + col] = v0;
            *(float2*)&hp[(size_t)(row + 8) * H_ + col] = v1;
        }
    }
}

// ======================= small kernels =======================
__global__ void k_zero() {
    int i = blockIdx.x * blockDim.x + threadIdx.x;
    if (i < B_ * H_) g_r[i] = 0.f;
}

__global__ void k_router_head(const float* __restrict__ fcW,
                              const float* __restrict__ fcb,
                              float* __restrict__ out) {
    __shared__ float lg[B_][E_];
    int t = threadIdx.x;
    if (t < B_ * E_) {
        int b = t / E_, e = t % E_;
        float s = fcb[e];
        for (int h = 0; h < H_; h++) s += g_r[b * H_ + h] * fcW[h * E_ + e];
        lg[b][e] = s;
    }
    __syncthreads();
    if (t < B_) {
        int b = t;
        float m = lg[b][0];
        #pragma unroll
        for (int e = 1; e < E_; e++) m = fmaxf(m, lg[b][e]);
        float p[E_]; float s = 0.f;
        #pragma unroll
        for (int e = 0; e < E_; e++) { p[e] = expf(lg[b][e] - m); s += p[e]; }
        float inv = 1.f / s;
        #pragma unroll
        for (int e = 0; e < E_; e++) {
            p[e] *= inv;
            out[B_ * L_ + B_ * C_ + b * E_ + e] = p[e];
        }
        int i0 = 0;
        #pragma unroll
        for (int e = 1; e < E_; e++) if (p[e] > p[i0]) i0 = e;
        int i1 = (i0 == 0) ? 1 : 0;
        #pragma unroll
        for (int e = 0; e < E_; e++) if (e != i1 && e != i0 && p[e] > p[i1]) i1 = e;
        float denom = p[i0] + p[i1] + 1e-8f;
        g_sel_e[2 * b + 0] = i0; g_sel_w[2 * b + 0] = p[i0] / denom;
        g_sel_e[2 * b + 1] = i1; g_sel_w[2 * b + 1] = p[i1] / denom;
    }
    for (int i = t; i < B_ * L_ + B_ * C_; i += blockDim.x) out[i] = 0.f;
}

__global__ __launch_bounds__(256) void k_scores(
    const float* __restrict__ eWv, const float* __restrict__ ebv,
    const float* __restrict__ eWu, const float* __restrict__ ebu,
    const float* __restrict__ ew, const float* __restrict__ ebw) {
    extern __shared__ float hs[];      // [32][H_] = 64 KB
    __shared__ float part[32][8];
    const int pair = blockIdx.y;
    const int n0 = blockIdx.x * 32;
    const int e = g_sel_e[pair];
    const int tid = threadIdx.x;

    const float4* src = (const float4*)(g_h + ((size_t)pair * N_ + n0) * H_);
    float4* dst = (float4*)hs;
    for (int i = tid; i < 32 * H_ / 4; i += 256) dst[i] = src[i];
    __syncthreads();

    const int a = tid;
    const float* Wv = eWv + (size_t)e * H_ * A_ + a;
    const float* Wu = eWu + (size_t)e * H_ * A_ + a;
    float accV[32] = {}, accU[32] = {};
    for (int h = 0; h < H_; h += 2) {
        float wv0 = Wv[(size_t)h * A_],       wu0 = Wu[(size_t)h * A_];
        float wv1 = Wv[(size_t)(h + 1) * A_], wu1 = Wu[(size_t)(h + 1) * A_];
        #pragma unroll
        for (int r = 0; r < 32; r++) {
            float2 hv = *(const float2*)&hs[r * H_ + h];
            accV[r] += hv.x * wv0 + hv.y * wv1;
            accU[r] += hv.x * wu0 + hv.y * wu1;
        }
    }
    const float bv = ebv[e * A_ + a], bu = ebu[e * A_ + a], wgt = ew[e * A_ + a];
    const int lane = tid & 31, warp = tid >> 5;
    #pragma unroll
    for (int r = 0; r < 32; r++) {
        float av = tanhf(accV[r] + bv);
        float au = 1.f / (1.f + expf(-(accU[r] + bu)));
        float v = av * au * wgt;
        v += __shfl_xor_sync(0xffffffffu, v, 16);
        v += __shfl_xor_sync(0xffffffffu, v, 8);
        v += __shfl_xor_sync(0xffffffffu, v, 4);
        v += __shfl_xor_sync(0xffffffffu, v, 2);
        v += __shfl_xor_sync(0xffffffffu, v, 1);
        if (lane == 0) part[r][warp] = v;
    }
    __syncthreads();
    if (tid < 32) {
        float s = ebw[e];
        #pragma unroll
        for (int w = 0; w < 8; w++) s += part[tid][w];
        g_scores[pair * N_ + n0 + tid] = s;
    }
}

// ---------------------------------------------------------------------------
// K5a: per (pair, 128-col block): softmax over N (recomputed) + pooled GEMV
// ---------------------------------------------------------------------------
__global__ __launch_bounds__(256) void k_pool() {
    __shared__ float attn[N_];
    __shared__ float red[256];
    const int pair = blockIdx.y;
    const int col0 = blockIdx.x * 128;
    const int t = threadIdx.x;

    const float* sc = g_scores + pair * N_;
    float m = -1e30f;
    for (int i = t; i < N_; i += 256) { float v = sc[i]; attn[i] = v; m = fmaxf(m, v); }
    red[t] = m; __syncthreads();
    for (int s = 128; s > 0; s >>= 1) {
        if (t < s) red[t] = fmaxf(red[t], red[t + s]);
        __syncthreads();
    }
    m = red[0]; __syncthreads();
    float ssum = 0.f;
    for (int i = t; i < N_; i += 256) { float ev = expf(attn[i] - m); attn[i] = ev; ssum += ev; }
    red[t] = ssum; __syncthreads();
    for (int s = 128; s > 0; s >>= 1) {
        if (t < s) red[t] += red[t + s];
        __syncthreads();
    }
    const float inv = 1.f / red[0];
    __syncthreads();

    const int col = col0 + (t & 127), half = t >> 7;
    const float* hp = g_h + (size_t)pair * N_ * H_ + (size_t)half * 512 * H_ + col;
    float acc = 0.f;
    #pragma unroll 8
    for (int n = 0; n < 512; n++) acc += attn[half * 512 + n] * hp[(size_t)n * H_];
    red[t] = acc;
    __syncthreads();
    if (t < 128) g_pooled[pair * H_ + col] = (red[t] + red[t + 128]) * inv;
}

// ---------------------------------------------------------------------------
// K5b: per pair: latent/logit heads + weighted atomic combine into d_out
// ---------------------------------------------------------------------------
__global__ __launch_bounds__(64) void k_head(
    const float* __restrict__ eW2, const float* __restrict__ eb2,
    const float* __restrict__ eWc, const float* __restrict__ ebc,
    float* __restrict__ out) {
    __shared__ float lat[L_];
    const int pair = blockIdx.x;
    const int e = g_sel_e[pair], b = pair >> 1;
    const float w = g_sel_w[pair];
    const int t = threadIdx.x;

    const float* pl = g_pooled + pair * H_;
    float acc = eb2[e * L_ + t];
    #pragma unroll 4
    for (int h = 0; h < H_; h++) acc += pl[h] * eW2[((size_t)e * H_ + h) * L_ + t];
    float lv = fmaxf(acc, 0.f);
    lat[t] = lv;
    atomicAdd(&out[b * L_ + t], w * lv);
    __syncthreads();
    if (t < C_) {
        float a2 = ebc[e * C_ + t];
        #pragma unroll
        for (int l = 0; l < L_; l++) a2 += lat[l] * eWc[((size_t)e * L_ + l) * C_ + t];
        atomicAdd(&out[B_ * L_ + b * C_ + t], w * a2);
    }
}

// ---------------------------------------------------------------------------
extern "C" void kernel_launch(void* const* d_in, const int* in_sizes, int n_in,
                              void* d_out, int out_size) {
    const float* x        = (const float*)d_in[0];
    const float* router_W = (const float*)d_in[1];
    const float* router_b = (const float*)d_in[2];
    const float* fc_W     = (const float*)d_in[3];
    const float* fc_b     = (const float*)d_in[4];
    const float* eW1      = (const float*)d_in[5];
    const float* eb1      = (const float*)d_in[6];
    const float* eWv      = (const float*)d_in[7];
    const float* ebv      = (const float*)d_in[8];
    const float* eWu      = (const float*)d_in[9];
    const float* ebu      = (const float*)d_in[10];
    const float* ew       = (const float*)d_in[11];
    const float* ebw      = (const float*)d_in[12];
    const float* eW2      = (const float*)d_in[13];
    const float* eb2      = (const float*)d_in[14];
    const float* eWc      = (const float*)d_in[15];
    const float* ebc      = (const float*)d_in[16];
    float* out = (float*)d_out;

    static bool attr_done = false;
    if (!attr_done) {
        cudaFuncSetAttribute(k_scores, cudaFuncAttributeMaxDynamicSharedMemorySize,
                             32 * H_ * sizeof(float));
        cudaFuncSetAttribute(k_mm_router, cudaFuncAttributeMaxDynamicSharedMemorySize,
                             MM_SMEM);
        cudaFuncSetAttribute(k_mm_expert, cudaFuncAttributeMaxDynamicSharedMemorySize,
                             MM_SMEM);
        attr_done = true;
    }

    k_conv_x<<<(B_ * N_ * D_) / 1024, 256>>>(x);
    k_conv_w<<<dim3(D_ / 32, H_ / 32, E_ + 1), dim3(32, 8)>>>(router_W, eW1);
    k_zero<<<(B_ * H_ + 255) / 256, 256>>>();
    k_mm_router<<<dim3(H_ / 128, (B_ * N_) / 128), 256, MM_SMEM>>>(router_b);
    k_router_head<<<1, 256>>>(fc_W, fc_b, out);
    k_mm_expert<<<dim3(H_ / 128, N_ / 128, NPAIR), 256, MM_SMEM>>>(eb1);
    k_scores<<<dim3(N_ / 32, NPAIR), 256, 32 * H_ * sizeof(float)>>>(
        eWv, ebv, eWu, ebu, ew, ebw);
    k_pool<<<dim3(H_ / 128, NPAIR), 256>>>();
    k_head<<<NPAIR, 64>>>(eW2, eb2, eWc, ebc, out);
}

// round 13
// speedup vs baseline: 2.9037x; 1.3626x over previous
#include <cuda_runtime.h>
#include <cuda_bf16.h>
#include <math.h>
#include <stdint.h>

#define B_ 16
#define N_ 1024
#define D_ 2048
#define E_ 8
#define H_ 512
#define A_ 256
#define L_ 64
#define C_ 8
#define NPAIR 32   // B_ * TOP_K

// ---- scratch (static device globals; no allocation anywhere) ----
__device__ float g_r[B_ * H_];
__device__ float g_scores[NPAIR * N_];
__device__ float g_pooled[NPAIR * H_];
__device__ float g_av[(size_t)NPAIR * N_ * A_];        // 32 MB fp32
__device__ int   g_sel_e[NPAIR];
__device__ float g_sel_w[NPAIR];
__device__ __nv_bfloat16 g_xhi[(size_t)B_ * N_ * D_];  // 64 MB
__device__ __nv_bfloat16 g_xlo[(size_t)B_ * N_ * D_];  // 64 MB
__device__ __nv_bfloat16 g_hhi[(size_t)NPAIR * N_ * H_];  // 32 MB
__device__ __nv_bfloat16 g_hlo[(size_t)NPAIR * N_ * H_];  // 32 MB
__device__ __nv_bfloat16 g_w1t_hi[(size_t)E_ * H_ * D_];
__device__ __nv_bfloat16 g_w1t_lo[(size_t)E_ * H_ * D_];
__device__ __nv_bfloat16 g_rwt_hi[(size_t)H_ * D_];
__device__ __nv_bfloat16 g_rwt_lo[(size_t)H_ * D_];
__device__ __nv_bfloat16 g_wvt_hi[(size_t)E_ * A_ * H_];  // 2 MB each
__device__ __nv_bfloat16 g_wvt_lo[(size_t)E_ * A_ * H_];
__device__ __nv_bfloat16 g_wut_hi[(size_t)E_ * A_ * H_];
__device__ __nv_bfloat16 g_wut_lo[(size_t)E_ * A_ * H_];

// ======================= base-PTX helpers =======================
__device__ __forceinline__ uint32_t smem_to_u32(const void* p) {
    uint32_t a;
    asm("{ .reg .u64 t; cvta.to.shared.u64 t, %1; cvt.u32.u64 %0, t; }"
        : "=r"(a) : "l"(p));
    return a;
}
__device__ __forceinline__ void cp_async16(uint32_t dst, const void* src) {
    asm volatile("cp.async.ca.shared.global [%0], [%1], 16;"
                 :: "r"(dst), "l"(src) : "memory");
}
#define CP_COMMIT() asm volatile("cp.async.commit_group;" ::: "memory")
#define CP_WAIT1()  asm volatile("cp.async.wait_group 1;" ::: "memory")

__device__ __forceinline__ void ldmx4(uint32_t* r, uint32_t addr) {
    asm volatile("ldmatrix.sync.aligned.m8n8.x4.shared.b16 {%0,%1,%2,%3}, [%4];"
        : "=r"(r[0]), "=r"(r[1]), "=r"(r[2]), "=r"(r[3]) : "r"(addr));
}
__device__ __forceinline__ void mma_bf16(float* c, const uint32_t* a,
                                         const uint32_t* b) {
    asm volatile(
        "mma.sync.aligned.m16n8k16.row.col.f32.bf16.bf16.f32 "
        "{%0,%1,%2,%3}, {%4,%5,%6,%7}, {%8,%9}, {%0,%1,%2,%3};"
        : "+f"(c[0]), "+f"(c[1]), "+f"(c[2]), "+f"(c[3])
        : "r"(a[0]), "r"(a[1]), "r"(a[2]), "r"(a[3]),
          "r"(b[0]), "r"(b[1]));
}

// ======================= conversion kernels =======================
__global__ __launch_bounds__(256) void k_conv_x(const float* __restrict__ x) {
    size_t i = ((size_t)blockIdx.x * 256 + threadIdx.x) * 4;
    float4 v = *(const float4*)(x + i);
    __nv_bfloat16 h0 = __float2bfloat16(v.x), h1 = __float2bfloat16(v.y);
    __nv_bfloat16 h2 = __float2bfloat16(v.z), h3 = __float2bfloat16(v.w);
    __nv_bfloat16 l0 = __float2bfloat16(v.x - __bfloat162float(h0));
    __nv_bfloat16 l1 = __float2bfloat16(v.y - __bfloat162float(h1));
    __nv_bfloat16 l2 = __float2bfloat16(v.z - __bfloat162float(h2));
    __nv_bfloat16 l3 = __float2bfloat16(v.w - __bfloat162float(h3));
    *(__nv_bfloat162*)(g_xhi + i)     = __nv_bfloat162(h0, h1);
    *(__nv_bfloat162*)(g_xhi + i + 2) = __nv_bfloat162(h2, h3);
    *(__nv_bfloat162*)(g_xlo + i)     = __nv_bfloat162(l0, l1);
    *(__nv_bfloat162*)(g_xlo + i + 2) = __nv_bfloat162(l2, l3);
}

// transpose + split W1: src [D_,H_] row-major -> dst [H_,D_] (K-major)
__global__ void k_conv_w(const float* __restrict__ routerW,
                         const float* __restrict__ eW1) {
    __shared__ float t[32][33];
    const int z = blockIdx.z;
    const float* src = z ? (eW1 + (size_t)(z - 1) * D_ * H_) : routerW;
    __nv_bfloat16* dh = z ? (g_w1t_hi + (size_t)(z - 1) * H_ * D_) : g_rwt_hi;
    __nv_bfloat16* dl = z ? (g_w1t_lo + (size_t)(z - 1) * H_ * D_) : g_rwt_lo;
    const int k0 = blockIdx.x * 32, n0 = blockIdx.y * 32;
    #pragma unroll
    for (int i = 0; i < 4; i++) {
        int k = k0 + threadIdx.y + i * 8;
        t[threadIdx.y + i * 8][threadIdx.x] = src[(size_t)k * H_ + n0 + threadIdx.x];
    }
    __syncthreads();
    #pragma unroll
    for (int i = 0; i < 4; i++) {
        int n = n0 + threadIdx.y + i * 8;
        float v = t[threadIdx.x][threadIdx.y + i * 8];
        __nv_bfloat16 hv = __float2bfloat16(v);
        __nv_bfloat16 lv = __float2bfloat16(v - __bfloat162float(hv));
        dh[(size_t)n * D_ + k0 + threadIdx.x] = hv;
        dl[(size_t)n * D_ + k0 + threadIdx.x] = lv;
    }
}

// transpose + split Wv/Wu: src [H_,A_] -> dst [A_,H_] (K-major)
// z: bit3 = V/U select, bits 0-2 = expert
__global__ void k_conv_wsc(const float* __restrict__ eWv,
                           const float* __restrict__ eWu) {
    __shared__ float t[32][33];
    const int z = blockIdx.z;
    const int e = z & 7, isU = z >> 3;
    const float* src = (isU ? eWu : eWv) + (size_t)e * H_ * A_;
    __nv_bfloat16* dh = (isU ? g_wut_hi : g_wvt_hi) + (size_t)e * A_ * H_;
    __nv_bfloat16* dl = (isU ? g_wut_lo : g_wvt_lo) + (size_t)e * A_ * H_;
    const int h0 = blockIdx.x * 32, a0 = blockIdx.y * 32;
    #pragma unroll
    for (int i = 0; i < 4; i++) {
        int h = h0 + threadIdx.y + i * 8;
        t[threadIdx.y + i * 8][threadIdx.x] = src[(size_t)h * A_ + a0 + threadIdx.x];
    }
    __syncthreads();
    #pragma unroll
    for (int i = 0; i < 4; i++) {
        int a = a0 + threadIdx.y + i * 8;
        float v = t[threadIdx.x][threadIdx.y + i * 8];
        __nv_bfloat16 hv = __float2bfloat16(v);
        __nv_bfloat16 lv = __float2bfloat16(v - __bfloat162float(hv));
        dh[(size_t)a * H_ + h0 + threadIdx.x] = hv;
        dl[(size_t)a * H_ + h0 + threadIdx.x] = lv;
    }
}

// ======================= mma.sync GEMM core =======================
// Block tile 128x128, K-chunks of 32 bf16. 8 warps, warp tile 32x64.
// 2-stage cp.async pipeline; ldmatrix fragment loads interleaved with MMAs.
#define ROWB   80
#define ARRB   (128 * ROWB)     // 10240
#define STAGEB (4 * ARRB)       // 40960
#define MM_SMEM (2 * STAGEB)    // 81920 -> 2 CTAs/SM

template<int LDK>
__device__ __forceinline__ void mm_load_stage(
    uint32_t sb, int stg, int k0, int tid,
    const __nv_bfloat16* Ah, const __nv_bfloat16* Al,
    const __nv_bfloat16* Bh, const __nv_bfloat16* Bl) {
    const __nv_bfloat16* ps[4] = {Ah, Al, Bh, Bl};
    uint32_t base = sb + stg * STAGEB;
    int row0 = tid >> 2, c16 = tid & 3;
    #pragma unroll
    for (int arr = 0; arr < 4; arr++) {
        #pragma unroll
        for (int half = 0; half < 2; half++) {
            int row = row0 + half * 64;
            cp_async16(base + arr * ARRB + row * ROWB + c16 * 16,
                       ps[arr] + (size_t)row * LDK + k0 + c16 * 8);
        }
    }
}

template<int LDK, int NCHUNK>
__device__ __forceinline__ void mm_core(
    const __nv_bfloat16* __restrict__ Ah, const __nv_bfloat16* __restrict__ Al,
    const __nv_bfloat16* __restrict__ Bh, const __nv_bfloat16* __restrict__ Bl,
    uint32_t sb, int tid, float acc[2][8][4]) {
    const int lane = tid & 31, wid = tid >> 5;
    const int wm = wid & 3, wn = wid >> 2;

    mm_load_stage<LDK>(sb, 0, 0, tid, Ah, Al, Bh, Bl);  CP_COMMIT();
    mm_load_stage<LDK>(sb, 1, 32, tid, Ah, Al, Bh, Bl); CP_COMMIT();

    const int a_row = lane & 15, a_kb = (lane >> 4) * 16;          // bytes
    const int b_row = ((lane >> 4) & 1) * 8 + (lane & 7);
    const int b_kb = ((lane >> 3) & 1) * 16;                       // bytes

    for (int s = 0; s < NCHUNK; s++) {
        CP_WAIT1();
        __syncthreads();
        const uint32_t b0 = sb + (s & 1) * STAGEB;
        #pragma unroll
        for (int ks = 0; ks < 2; ks++) {       // two k16 slices
            uint32_t ah[2][4], al[2][4], bh[8][2], bl[8][2];
            uint32_t ra[2], rb4[4];
            #pragma unroll
            for (int mt = 0; mt < 2; mt++) {
                ra[mt] = b0 + (wm * 32 + mt * 16 + a_row) * ROWB + ks * 32 + a_kb;
                ldmx4(ah[mt], ra[mt]);
            }
            #pragma unroll
            for (int np = 0; np < 4; np++) {
                rb4[np] = b0 + 2 * ARRB +
                    (wn * 64 + np * 16 + b_row) * ROWB + ks * 32 + b_kb;
                ldmx4(&bh[2 * np][0], rb4[np]);
            }
            #pragma unroll
            for (int mt = 0; mt < 2; mt++)
                #pragma unroll
                for (int nt = 0; nt < 8; nt++)
                    mma_bf16(acc[mt][nt], ah[mt], bh[nt]);
            #pragma unroll
            for (int mt = 0; mt < 2; mt++)
                ldmx4(al[mt], ra[mt] + ARRB);
            #pragma unroll
            for (int mt = 0; mt < 2; mt++)
                #pragma unroll
                for (int nt = 0; nt < 8; nt++)
                    mma_bf16(acc[mt][nt], al[mt], bh[nt]);
            #pragma unroll
            for (int np = 0; np < 4; np++)
                ldmx4(&bl[2 * np][0], rb4[np] + ARRB);
            #pragma unroll
            for (int mt = 0; mt < 2; mt++)
                #pragma unroll
                for (int nt = 0; nt < 8; nt++)
                    mma_bf16(acc[mt][nt], ah[mt], bl[nt]);
        }
        __syncthreads();
        if (s + 2 < NCHUNK)
            mm_load_stage<LDK>(sb, s & 1, (s + 2) * 32, tid, Ah, Al, Bh, Bl);
        CP_COMMIT();
    }
}

// ---------------------------------------------------------------------------
// K1: router GEMM: relu(x@W + b), mean over N -> atomic into g_r
// ---------------------------------------------------------------------------
__global__ __launch_bounds__(256, 2) void k_mm_router(const float* __restrict__ rb) {
    extern __shared__ char smem[];
    const uint32_t sb = smem_to_u32(smem);
    const int tid = threadIdx.x;
    const int n0 = blockIdx.x * 128, m0 = blockIdx.y * 128;

    float acc[2][8][4] = {};
    mm_core<D_, D_ / 32>(g_xhi + (size_t)m0 * D_, g_xlo + (size_t)m0 * D_,
                         g_rwt_hi + (size_t)n0 * D_, g_rwt_lo + (size_t)n0 * D_,
                         sb, tid, acc);

    const int lane = tid & 31, wid = tid >> 5;
    const int wn = wid >> 2;
    const int l4 = lane >> 2, q2 = (lane & 3) * 2;
    const int b = m0 / N_;
    #pragma unroll
    for (int nt = 0; nt < 8; nt++) {
        int col = n0 + wn * 64 + nt * 8 + q2;
        float bx = rb[col], by = rb[col + 1];
        float s0 = 0.f, s1 = 0.f;
        #pragma unroll
        for (int mt = 0; mt < 2; mt++) {
            s0 += fmaxf(acc[mt][nt][0] + bx, 0.f) + fmaxf(acc[mt][nt][2] + bx, 0.f);
            s1 += fmaxf(acc[mt][nt][1] + by, 0.f) + fmaxf(acc[mt][nt][3] + by, 0.f);
        }
        s0 += __shfl_xor_sync(0xffffffffu, s0, 4);
        s0 += __shfl_xor_sync(0xffffffffu, s0, 8);
        s0 += __shfl_xor_sync(0xffffffffu, s0, 16);
        s1 += __shfl_xor_sync(0xffffffffu, s1, 4);
        s1 += __shfl_xor_sync(0xffffffffu, s1, 8);
        s1 += __shfl_xor_sync(0xffffffffu, s1, 16);
        if (l4 == 0) {
            atomicAdd(&g_r[b * H_ + col],     s0 * (1.f / N_));
            atomicAdd(&g_r[b * H_ + col + 1], s1 * (1.f / N_));
        }
    }
}

// ---------------------------------------------------------------------------
// K3: expert GEMM: h = relu(x_b @ eW1[e] + eb1[e]) -> split-bf16 g_hhi/g_hlo
// ---------------------------------------------------------------------------
__global__ __launch_bounds__(256, 2) void k_mm_expert(const float* __restrict__ eb1) {
    extern __shared__ char smem[];
    const uint32_t sb = smem_to_u32(smem);
    const int tid = threadIdx.x;
    const int pair = blockIdx.z;
    const int e = g_sel_e[pair], b = pair >> 1;
    const int n0 = blockIdx.x * 128, m0 = blockIdx.y * 128;

    float acc[2][8][4] = {};
    mm_core<D_, D_ / 32>(g_xhi + ((size_t)b * N_ + m0) * D_,
                         g_xlo + ((size_t)b * N_ + m0) * D_,
                         g_w1t_hi + ((size_t)e * H_ + n0) * D_,
                         g_w1t_lo + ((size_t)e * H_ + n0) * D_, sb, tid, acc);

    const int lane = tid & 31, wid = tid >> 5;
    const int wm = wid & 3, wn = wid >> 2;
    const int l4 = lane >> 2, q2 = (lane & 3) * 2;
    __nv_bfloat16* hh = g_hhi + (size_t)pair * N_ * H_;
    __nv_bfloat16* hl = g_hlo + (size_t)pair * N_ * H_;
    #pragma unroll
    for (int mt = 0; mt < 2; mt++) {
        #pragma unroll
        for (int rh = 0; rh < 2; rh++) {
            int row = m0 + wm * 32 + mt * 16 + l4 + rh * 8;
            #pragma unroll
            for (int nt = 0; nt < 8; nt++) {
                int col = n0 + wn * 64 + nt * 8 + q2;
                float v0 = fmaxf(acc[mt][nt][2 * rh] + eb1[e * H_ + col], 0.f);
                float v1 = fmaxf(acc[mt][nt][2 * rh + 1] + eb1[e * H_ + col + 1], 0.f);
                __nv_bfloat16 h0 = __float2bfloat16(v0);
                __nv_bfloat16 h1 = __float2bfloat16(v1);
                __nv_bfloat16 l0 = __float2bfloat16(v0 - __bfloat162float(h0));
                __nv_bfloat16 l1 = __float2bfloat16(v1 - __bfloat162float(h1));
                *(__nv_bfloat162*)&hh[(size_t)row * H_ + col] = __nv_bfloat162(h0, h1);
                *(__nv_bfloat162*)&hl[(size_t)row * H_ + col] = __nv_bfloat162(l0, l1);
            }
        }
    }
}

// ---------------------------------------------------------------------------
// K4a: Av GEMM: av = tanh(h @ Wv + bv) -> g_av fp32
// grid (A_/128=2, N_/128=8, NPAIR)
// ---------------------------------------------------------------------------
__global__ __launch_bounds__(256, 2) void k_mm_scoreV(const float* __restrict__ ebv) {
    extern __shared__ char smem[];
    const uint32_t sb = smem_to_u32(smem);
    const int tid = threadIdx.x;
    const int pair = blockIdx.z;
    const int e = g_sel_e[pair];
    const int n0 = blockIdx.x * 128, m0 = blockIdx.y * 128;

    float acc[2][8][4] = {};
    mm_core<H_, H_ / 32>(g_hhi + ((size_t)pair * N_ + m0) * H_,
                         g_hlo + ((size_t)pair * N_ + m0) * H_,
                         g_wvt_hi + ((size_t)e * A_ + n0) * H_,
                         g_wvt_lo + ((size_t)e * A_ + n0) * H_, sb, tid, acc);

    const int lane = tid & 31, wid = tid >> 5;
    const int wm = wid & 3, wn = wid >> 2;
    const int l4 = lane >> 2, q2 = (lane & 3) * 2;
    float* av = g_av + (size_t)pair * N_ * A_;
    #pragma unroll
    for (int mt = 0; mt < 2; mt++) {
        #pragma unroll
        for (int rh = 0; rh < 2; rh++) {
            int row = m0 + wm * 32 + mt * 16 + l4 + rh * 8;
            #pragma unroll
            for (int nt = 0; nt < 8; nt++) {
                int col = n0 + wn * 64 + nt * 8 + q2;
                float2 v;
                v.x = tanhf(acc[mt][nt][2 * rh]     + ebv[e * A_ + col]);
                v.y = tanhf(acc[mt][nt][2 * rh + 1] + ebv[e * A_ + col + 1]);
                *(float2*)&av[(size_t)row * A_ + col] = v;
            }
        }
    }
}

// ---------------------------------------------------------------------------
// K4b: Au GEMM + combine: scores += sum_a av * sigmoid(au) * ew[a]
// ---------------------------------------------------------------------------
__global__ __launch_bounds__(256, 2) void k_mm_scoreU(
    const float* __restrict__ ebu, const float* __restrict__ ew) {
    extern __shared__ char smem[];
    const uint32_t sb = smem_to_u32(smem);
    const int tid = threadIdx.x;
    const int pair = blockIdx.z;
    const int e = g_sel_e[pair];
    const int n0 = blockIdx.x * 128, m0 = blockIdx.y * 128;

    float acc[2][8][4] = {};
    mm_core<H_, H_ / 32>(g_hhi + ((size_t)pair * N_ + m0) * H_,
                         g_hlo + ((size_t)pair * N_ + m0) * H_,
                         g_wut_hi + ((size_t)e * A_ + n0) * H_,
                         g_wut_lo + ((size_t)e * A_ + n0) * H_, sb, tid, acc);

    const int lane = tid & 31, wid = tid >> 5;
    const int wm = wid & 3, wn = wid >> 2;
    const int l4 = lane >> 2, q2 = (lane & 3) * 2;
    const float* av = g_av + (size_t)pair * N_ * A_;
    const float* bup = ebu + e * A_;
    const float* ewp = ew + e * A_;
    #pragma unroll
    for (int mt = 0; mt < 2; mt++) {
        #pragma unroll
        for (int rh = 0; rh < 2; rh++) {
            int row = m0 + wm * 32 + mt * 16 + l4 + rh * 8;
            float s = 0.f;
            #pragma unroll
            for (int nt = 0; nt < 8; nt++) {
                int col = n0 + wn * 64 + nt * 8 + q2;
                float2 avv = *(const float2*)&av[(size_t)row * A_ + col];
                float u0 = 1.f / (1.f + expf(-(acc[mt][nt][2 * rh]     + bup[col])));
                float u1 = 1.f / (1.f + expf(-(acc[mt][nt][2 * rh + 1] + bup[col + 1])));
                s += avv.x * u0 * ewp[col] + avv.y * u1 * ewp[col + 1];
            }
            s += __shfl_xor_sync(0xffffffffu, s, 1);
            s += __shfl_xor_sync(0xffffffffu, s, 2);
            if ((lane & 3) == 0) atomicAdd(&g_scores[pair * N_ + row], s);
        }
    }
}

// ======================= small kernels =======================
__global__ void k_zero() {
    int i = blockIdx.x * blockDim.x + threadIdx.x;
    if (i < B_ * H_) g_r[i] = 0.f;
}

// seed g_scores with ebw[e] (after router selection)
__global__ void k_score_init(const float* __restrict__ ebw) {
    int i = blockIdx.x * blockDim.x + threadIdx.x;
    if (i < NPAIR * N_) g_scores[i] = ebw[g_sel_e[i / N_]];
}

__global__ void k_router_head(const float* __restrict__ fcW,
                              const float* __restrict__ fcb,
                              float* __restrict__ out) {
    __shared__ float lg[B_][E_];
    int t = threadIdx.x;
    if (t < B_ * E_) {
        int b = t / E_, e = t % E_;
        float s = fcb[e];
        for (int h = 0; h < H_; h++) s += g_r[b * H_ + h] * fcW[h * E_ + e];
        lg[b][e] = s;
    }
    __syncthreads();
    if (t < B_) {
        int b = t;
        float m = lg[b][0];
        #pragma unroll
        for (int e = 1; e < E_; e++) m = fmaxf(m, lg[b][e]);
        float p[E_]; float s = 0.f;
        #pragma unroll
        for (int e = 0; e < E_; e++) { p[e] = expf(lg[b][e] - m); s += p[e]; }
        float inv = 1.f / s;
        #pragma unroll
        for (int e = 0; e < E_; e++) {
            p[e] *= inv;
            out[B_ * L_ + B_ * C_ + b * E_ + e] = p[e];
        }
        int i0 = 0;
        #pragma unroll
        for (int e = 1; e < E_; e++) if (p[e] > p[i0]) i0 = e;
        int i1 = (i0 == 0) ? 1 : 0;
        #pragma unroll
        for (int e = 0; e < E_; e++) if (e != i1 && e != i0 && p[e] > p[i1]) i1 = e;
        float denom = p[i0] + p[i1] + 1e-8f;
        g_sel_e[2 * b + 0] = i0; g_sel_w[2 * b + 0] = p[i0] / denom;
        g_sel_e[2 * b + 1] = i1; g_sel_w[2 * b + 1] = p[i1] / denom;
    }
    for (int i = t; i < B_ * L_ + B_ * C_; i += blockDim.x) out[i] = 0.f;
}

// ---------------------------------------------------------------------------
// K5a: per (pair, 128-col block): softmax over N (recomputed) + pooled GEMV
// reads split-bf16 h
// ---------------------------------------------------------------------------
__global__ __launch_bounds__(256) void k_pool() {
    __shared__ float attn[N_];
    __shared__ float red[256];
    __shared__ float2 red2[256];
    const int pair = blockIdx.y;
    const int col0 = blockIdx.x * 128;
    const int t = threadIdx.x;

    const float* sc = g_scores + pair * N_;
    float m = -1e30f;
    for (int i = t; i < N_; i += 256) { float v = sc[i]; attn[i] = v; m = fmaxf(m, v); }
    red[t] = m; __syncthreads();
    for (int s = 128; s > 0; s >>= 1) {
        if (t < s) red[t] = fmaxf(red[t], red[t + s]);
        __syncthreads();
    }
    m = red[0]; __syncthreads();
    float ssum = 0.f;
    for (int i = t; i < N_; i += 256) { float ev = expf(attn[i] - m); attn[i] = ev; ssum += ev; }
    red[t] = ssum; __syncthreads();
    for (int s = 128; s > 0; s >>= 1) {
        if (t < s) red[t] += red[t + s];
        __syncthreads();
    }
    const float inv = 1.f / red[0];
    __syncthreads();

    const int c2 = (t & 63) * 2, q = t >> 6;
    const __nv_bfloat162* hh = (const __nv_bfloat162*)(g_hhi + (size_t)pair * N_ * H_);
    const __nv_bfloat162* hl = (const __nv_bfloat162*)(g_hlo + (size_t)pair * N_ * H_);
    const int base = (col0 + c2) >> 1;
    float2 acc = {0.f, 0.f};
    #pragma unroll 4
    for (int n = q * 256; n < q * 256 + 256; n++) {
        float wn = attn[n];
        __nv_bfloat162 a = hh[(size_t)n * (H_ / 2) + base];
        __nv_bfloat162 b = hl[(size_t)n * (H_ / 2) + base];
        acc.x += wn * (__bfloat162float(a.x) + __bfloat162float(b.x));
        acc.y += wn * (__bfloat162float(a.y) + __bfloat162float(b.y));
    }
    red2[t] = acc;
    __syncthreads();
    if (t < 64) {
        float sx = red2[t].x + red2[t + 64].x + red2[t + 128].x + red2[t + 192].x;
        float sy = red2[t].y + red2[t + 64].y + red2[t + 128].y + red2[t + 192].y;
        g_pooled[pair * H_ + col0 + t * 2]     = sx * inv;
        g_pooled[pair * H_ + col0 + t * 2 + 1] = sy * inv;
    }
}

// ---------------------------------------------------------------------------
// K5b: per pair: latent/logit heads + weighted atomic combine into d_out
// ---------------------------------------------------------------------------
__global__ __launch_bounds__(64) void k_head(
    const float* __restrict__ eW2, const float* __restrict__ eb2,
    const float* __restrict__ eWc, const float* __restrict__ ebc,
    float* __restrict__ out) {
    __shared__ float lat[L_];
    const int pair = blockIdx.x;
    const int e = g_sel_e[pair], b = pair >> 1;
    const float w = g_sel_w[pair];
    const int t = threadIdx.x;

    const float* pl = g_pooled + pair * H_;
    float acc = eb2[e * L_ + t];
    #pragma unroll 4
    for (int h = 0; h < H_; h++) acc += pl[h] * eW2[((size_t)e * H_ + h) * L_ + t];
    float lv = fmaxf(acc, 0.f);
    lat[t] = lv;
    atomicAdd(&out[b * L_ + t], w * lv);
    __syncthreads();
    if (t < C_) {
        float a2 = ebc[e * C_ + t];
        #pragma unroll
        for (int l = 0; l < L_; l++) a2 += lat[l] * eWc[((size_t)e * L_ + l) * C_ + t];
        atomicAdd(&out[B_ * L_ + b * C_ + t], w * a2);
    }
}

// ---------------------------------------------------------------------------
extern "C" void kernel_launch(void* const* d_in, const int* in_sizes, int n_in,
                              void* d_out, int out_size) {
    const float* x        = (const float*)d_in[0];
    const float* router_W = (const float*)d_in[1];
    const float* router_b = (const float*)d_in[2];
    const float* fc_W     = (const float*)d_in[3];
    const float* fc_b     = (const float*)d_in[4];
    const float* eW1      = (const float*)d_in[5];
    const float* eb1      = (const float*)d_in[6];
    const float* eWv      = (const float*)d_in[7];
    const float* ebv      = (const float*)d_in[8];
    const float* eWu      = (const float*)d_in[9];
    const float* ebu      = (const float*)d_in[10];
    const float* ew       = (const float*)d_in[11];
    const float* ebw      = (const float*)d_in[12];
    const float* eW2      = (const float*)d_in[13];
    const float* eb2      = (const float*)d_in[14];
    const float* eWc      = (const float*)d_in[15];
    const float* ebc      = (const float*)d_in[16];
    float* out = (float*)d_out;

    static bool attr_done = false;
    if (!attr_done) {
        cudaFuncSetAttribute(k_mm_router, cudaFuncAttributeMaxDynamicSharedMemorySize,
                             MM_SMEM);
        cudaFuncSetAttribute(k_mm_expert, cudaFuncAttributeMaxDynamicSharedMemorySize,
                             MM_SMEM);
        cudaFuncSetAttribute(k_mm_scoreV, cudaFuncAttributeMaxDynamicSharedMemorySize,
                             MM_SMEM);
        cudaFuncSetAttribute(k_mm_scoreU, cudaFuncAttributeMaxDynamicSharedMemorySize,
                             MM_SMEM);
        attr_done = true;
    }

    k_conv_x<<<(B_ * N_ * D_) / 1024, 256>>>(x);
    k_conv_w<<<dim3(D_ / 32, H_ / 32, E_ + 1), dim3(32, 8)>>>(router_W, eW1);
    k_conv_wsc<<<dim3(H_ / 32, A_ / 32, 2 * E_), dim3(32, 8)>>>(eWv, eWu);
    k_zero<<<(B_ * H_ + 255) / 256, 256>>>();
    k_mm_router<<<dim3(H_ / 128, (B_ * N_) / 128), 256, MM_SMEM>>>(router_b);
    k_router_head<<<1, 256>>>(fc_W, fc_b, out);
    k_score_init<<<(NPAIR * N_) / 256, 256>>>(ebw);
    k_mm_expert<<<dim3(H_ / 128, N_ / 128, NPAIR), 256, MM_SMEM>>>(eb1);
    k_mm_scoreV<<<dim3(A_ / 128, N_ / 128, NPAIR), 256, MM_SMEM>>>(ebv);
    k_mm_scoreU<<<dim3(A_ / 128, N_ / 128, NPAIR), 256, MM_SMEM>>>(ebu, ew);
    k_pool<<<dim3(H_ / 128, NPAIR), 256>>>();
    k_head<<<NPAIR, 64>>>(eW2, eb2, eWc, ebc, out);
}